// round 8
// baseline (speedup 1.0000x reference)
#include <cuda_runtime.h>
#include <math.h>

#define T_LEN   8196
#define WIN     8
#define STRIDE  4
#define NW      2048
#define BATCH   4096
#define IN_F    72
#define HID     128
#define G3      384
#define FEAT    30
#define STEPS   8
#define LOG2E   1.44269504f
#define LN2     0.693147180559945f

#define NSTRIP  32               // soft-DTW strips of 64 rows
#define SS_CHUNKS 132            // 132 chunks x 8 supersteps = 1056
#define D_TPAD  1064             // superstep dim incl. prefetch pad

// ---------------- static scratch ----------------
__device__ float g_seq  [STEPS * BATCH * IN_F];
__device__ float g_gi   [STEPS * BATCH * G3];
__device__ float g_h1all[STEPS * BATCH * HID];
__device__ float g_feat [BATCH * FEAT];
__device__ float g_Ds   [NSTRIP * D_TPAD * 32 * 4];   // skewed 2x2-block p = 2^(-d*lg2e)
__device__ float g_WhhT1[HID * G3];
__device__ float g_WhhT2[HID * G3];
__device__ float4 g_row4[NSTRIP * 1024];              // handoff: (E_b0, E_b1, M, 0) raw
__device__ int   g_flag2[NSTRIP * 32];                // flags 128B apart

// ---------------- PTX helpers ----------------
__device__ __forceinline__ float ex2f(float x) {
    float r; asm("ex2.approx.ftz.f32 %0, %1;" : "=f"(r) : "f"(x)); return r;
}
__device__ __forceinline__ float lg2f(float x) {
    float r; asm("lg2.approx.ftz.f32 %0, %1;" : "=f"(r) : "f"(x)); return r;
}
__device__ __forceinline__ int ldacq(const int* p) {
    int v; asm volatile("ld.acquire.gpu.global.b32 %0, [%1];" : "=r"(v) : "l"(p) : "memory"); return v;
}
__device__ __forceinline__ void stg_pred(float* p, float v, int pred) {
    asm volatile("{\n\t.reg .pred p;\n\tsetp.ne.s32 p, %0, 0;\n\t@p st.global.f32 [%1], %2;\n\t}"
                 :: "r"(pred), "l"(p), "f"(v) : "memory");
}
__device__ __forceinline__ void stg4_pred(float4* p, float a, float b, float c, int pred) {
    asm volatile("{\n\t.reg .pred p;\n\tsetp.ne.s32 p, %0, 0;\n\t@p st.global.v4.f32 [%1], {%2, %3, %4, %5};\n\t}"
                 :: "r"(pred), "l"(p), "f"(a), "f"(b), "f"(c), "f"(0.f) : "memory");
}
__device__ __forceinline__ void red_rel_pred(int* p, int pred) {
    asm volatile("{\n\t.reg .pred p;\n\tsetp.ne.s32 p, %0, 0;\n\t@p red.release.gpu.global.add.u32 [%1], 1;\n\t}"
                 :: "r"(pred), "l"(p) : "memory");
}

// ---------------- prep ----------------
__global__ void prep_kernel(const float* __restrict__ x, const float* __restrict__ y,
                            const float* __restrict__ Whh1, const float* __restrict__ Whh2) {
    int idx = blockIdx.x * blockDim.x + threadIdx.x;
    const int total = STEPS * BATCH * IN_F;
    if (idx < total) {
        int f = idx % IN_F;
        int b = (idx / IN_F) % BATCH;
        int s = idx / (IN_F * BATCH);
        const float* src = (b < NW) ? x : y;
        int w = b & (NW - 1);
        g_seq[idx] = src[(size_t)f * T_LEN + w * STRIDE + s];
    }
    if (idx < HID * G3) {
        int k = idx / G3, n = idx % G3;
        g_WhhT1[idx] = Whh1[(size_t)n * HID + k];
        g_WhhT2[idx] = Whh2[(size_t)n * HID + k];
    }
    if (idx < NSTRIP) g_flag2[idx * 32] = 0;
}

// ---------------- SGEMM (double-buffered, warp-tiled): C = A@B^T + bias ----------------
template<int BK>
__global__ void __launch_bounds__(256)
sgemm_db(const float* __restrict__ A, const float* __restrict__ Bw,
         const float* __restrict__ bias, float* __restrict__ C,
         int M, int N, int K) {
    constexpr int BM = 128, BN = 128;
    constexpr int PAD = 4;
    constexpr int C4S = BK / 4;
    constexpr int NL  = (BM * BK / 4) / 256;

    __shared__ float As[2][BK][BM + PAD];
    __shared__ float Bs[2][BK][BN + PAD];

    const int tid = threadIdx.x;
    const int rb = blockIdx.y * BM;
    const int cb = blockIdx.x * BN;
    const int warp = tid >> 5, lane = tid & 31;
    const int wr = (warp & 3) * 32;
    const int wc = (warp >> 2) * 64;
    const int lr = ((lane >> 3) & 3) * 8;
    const int lc = (lane & 7) * 8;

    const int nt = K / BK;

    float4 aR[NL], bR[NL];
    int lrow[NL], lcc[NL];
#pragma unroll
    for (int i = 0; i < NL; ++i) {
        int idx = tid + i * 256;
        lrow[i] = idx / C4S;
        lcc[i]  = idx % C4S;
    }

    auto loadT = [&](int t) {
#pragma unroll
        for (int i = 0; i < NL; ++i) {
            aR[i] = *(const float4*)&A[(size_t)(rb + lrow[i]) * K + t * BK + lcc[i] * 4];
            bR[i] = *(const float4*)&Bw[(size_t)(cb + lrow[i]) * K + t * BK + lcc[i] * 4];
        }
    };
    auto storeT = [&](int buf) {
#pragma unroll
        for (int i = 0; i < NL; ++i) {
            As[buf][lcc[i] * 4 + 0][lrow[i]] = aR[i].x;
            As[buf][lcc[i] * 4 + 1][lrow[i]] = aR[i].y;
            As[buf][lcc[i] * 4 + 2][lrow[i]] = aR[i].z;
            As[buf][lcc[i] * 4 + 3][lrow[i]] = aR[i].w;
            Bs[buf][lcc[i] * 4 + 0][lrow[i]] = bR[i].x;
            Bs[buf][lcc[i] * 4 + 1][lrow[i]] = bR[i].y;
            Bs[buf][lcc[i] * 4 + 2][lrow[i]] = bR[i].z;
            Bs[buf][lcc[i] * 4 + 3][lrow[i]] = bR[i].w;
        }
    };

    float acc[8][8];
#pragma unroll
    for (int i = 0; i < 8; i++)
#pragma unroll
        for (int j = 0; j < 8; j++) acc[i][j] = 0.f;

    loadT(0);
    storeT(0);
    __syncthreads();

    for (int t = 0; t < nt; ++t) {
        const int cur = t & 1;
        if (t + 1 < nt) loadT(t + 1);
#pragma unroll
        for (int kk = 0; kk < BK; ++kk) {
            float4 a0 = *(const float4*)&As[cur][kk][wr + lr];
            float4 a1 = *(const float4*)&As[cur][kk][wr + lr + 4];
            float4 b0 = *(const float4*)&Bs[cur][kk][wc + lc];
            float4 b1 = *(const float4*)&Bs[cur][kk][wc + lc + 4];
            float ra[8]  = {a0.x, a0.y, a0.z, a0.w, a1.x, a1.y, a1.z, a1.w};
            float rbv[8] = {b0.x, b0.y, b0.z, b0.w, b1.x, b1.y, b1.z, b1.w};
#pragma unroll
            for (int i = 0; i < 8; i++)
#pragma unroll
                for (int j = 0; j < 8; j++)
                    acc[i][j] += ra[i] * rbv[j];
        }
        if (t + 1 < nt) storeT((t + 1) & 1);
        __syncthreads();
    }

    float bv[8];
#pragma unroll
    for (int j = 0; j < 8; j++) bv[j] = bias[cb + wc + lc + j];
#pragma unroll
    for (int i = 0; i < 8; i++) {
        int row = rb + wr + lr + i;
        float4 o0 = make_float4(acc[i][0] + bv[0], acc[i][1] + bv[1],
                                acc[i][2] + bv[2], acc[i][3] + bv[3]);
        float4 o1 = make_float4(acc[i][4] + bv[4], acc[i][5] + bv[5],
                                acc[i][6] + bv[6], acc[i][7] + bv[7]);
        *(float4*)&C[(size_t)row * N + cb + wc + lc]     = o0;
        *(float4*)&C[(size_t)row * N + cb + wc + lc + 4] = o1;
    }
}

// ---------------- persistent GRU layer (split-K; R3-form inner loop, regs<=128) ----------------
__global__ void __launch_bounds__(512)
gru_layer_kernel(const float* __restrict__ gi,
                 const float4* __restrict__ W4,    // [HID][G3] as float4
                 const float* __restrict__ bhh,
                 float* __restrict__ hall,
                 const float* __restrict__ W1,
                 const float* __restrict__ b1)
{
    extern __shared__ float sraw[];
    float (*hsm)[HID] = (float (*)[HID])sraw;
    float (*psum)[G3] = (float (*)[G3])(sraw + 32 * HID);

    const int tid = threadIdx.x;
    const int kh  = tid >> 8;
    const int gt  = tid & 255;
    const int tr  = gt >> 5;
    const int tc  = gt & 31;
    const int rb  = blockIdx.x * 32;
    const int kbase = kh * 64;
    const bool comb = (kh == 0) ? (tr < 4) : (tr >= 4);

    for (int m = tid; m < 32 * HID; m += 512) sraw[m] = 0.f;
    __syncthreads();

    float bq[3][4];
#pragma unroll
    for (int g = 0; g < 3; ++g) {
        float4 bb = *(const float4*)&bhh[g * HID + tc * 4];
        bq[g][0] = bb.x; bq[g][1] = bb.y; bq[g][2] = bb.z; bq[g][3] = bb.w;
    }

    for (int step = 0; step < STEPS; ++step) {
        float acc[4][3][4];
#pragma unroll
        for (int ii = 0; ii < 4; ++ii)
#pragma unroll
            for (int g = 0; g < 3; ++g)
#pragma unroll
                for (int o = 0; o < 4; ++o) acc[ii][g][o] = 0.f;

        // R3-form inner loop (measured 150.75us, no spills)
#pragma unroll 4
        for (int kk = 0; kk < 64; ++kk) {
            const int k = kbase + kk;
            float a[4];
#pragma unroll
            for (int ii = 0; ii < 4; ++ii) a[ii] = hsm[tr * 4 + ii][k];
#pragma unroll
            for (int g = 0; g < 3; ++g) {
                float4 b = __ldg(&W4[k * 96 + g * 32 + tc]);
#pragma unroll
                for (int ii = 0; ii < 4; ++ii) {
                    acc[ii][g][0] += a[ii] * b.x;
                    acc[ii][g][1] += a[ii] * b.y;
                    acc[ii][g][2] += a[ii] * b.z;
                    acc[ii][g][3] += a[ii] * b.w;
                }
            }
        }
        __syncthreads();

        if (!comb) {
#pragma unroll
            for (int ii = 0; ii < 4; ++ii) {
                const int r = tr * 4 + ii;
#pragma unroll
                for (int g = 0; g < 3; ++g)
                    *(float4*)&psum[r][g * HID + tc * 4] =
                        make_float4(acc[ii][g][0], acc[ii][g][1],
                                    acc[ii][g][2], acc[ii][g][3]);
            }
        }
        __syncthreads();

        if (comb) {
            const size_t rowbase = (size_t)step * BATCH + rb;
#pragma unroll
            for (int ii = 0; ii < 4; ++ii) {
                const int r = tr * 4 + ii;
                const float* gb = gi + (rowbase + r) * G3;
                float4 gr = __ldg((const float4*)(gb + tc * 4));
                float4 gz = __ldg((const float4*)(gb + HID + tc * 4));
                float4 gn = __ldg((const float4*)(gb + 2 * HID + tc * 4));
                float4 p0 = *(const float4*)&psum[r][0 * HID + tc * 4];
                float4 p1 = *(const float4*)&psum[r][1 * HID + tc * 4];
                float4 p2 = *(const float4*)&psum[r][2 * HID + tc * 4];
                float4 ho = *(const float4*)&hsm[r][tc * 4];
                float irv[4] = {gr.x, gr.y, gr.z, gr.w};
                float izv[4] = {gz.x, gz.y, gz.z, gz.w};
                float inv[4] = {gn.x, gn.y, gn.z, gn.w};
                float hv [4] = {ho.x, ho.y, ho.z, ho.w};
                float pr [4] = {p0.x, p0.y, p0.z, p0.w};
                float pz [4] = {p1.x, p1.y, p1.z, p1.w};
                float pn [4] = {p2.x, p2.y, p2.z, p2.w};
                float ov[4];
#pragma unroll
                for (int o = 0; o < 4; ++o) {
                    float hr = acc[ii][0][o] + pr[o] + bq[0][o];
                    float hz = acc[ii][1][o] + pz[o] + bq[1][o];
                    float hn = acc[ii][2][o] + pn[o] + bq[2][o];
                    float rg = 1.f / (1.f + __expf(-(irv[o] + hr)));
                    float zg = 1.f / (1.f + __expf(-(izv[o] + hz)));
                    float ng = tanhf(inv[o] + rg * hn);
                    ov[o] = (1.f - zg) * ng + zg * hv[o];
                }
                float4 hn4 = make_float4(ov[0], ov[1], ov[2], ov[3]);
                *(float4*)&hsm[r][tc * 4] = hn4;
                if (hall)
                    *(float4*)&hall[(rowbase + r) * HID + tc * 4] = hn4;
            }
        }
        __syncthreads();
    }

    if (W1) {
        for (int t = tid; t < 32 * FEAT; t += 512) {
            int r = t / FEAT, o = t % FEAT;
            float s = b1[o];
            const float* w = W1 + (size_t)o * HID;
#pragma unroll 8
            for (int k = 0; k < HID; ++k) s += hsm[r][k] * w[k];
            g_feat[(size_t)(rb + r) * FEAT + o] = s;
        }
    }
}

// ---------------- pairwise: store p = 2^(-d*log2e) in skewed 2x2-block layout ----------------
__global__ void pairdist_kernel() {
    __shared__ float s1[32][31];
    __shared__ float s2[32][31];
    int tid = threadIdx.y * 32 + threadIdx.x;
    int i0 = blockIdx.y * 32, j0 = blockIdx.x * 32;
    for (int idx = tid; idx < 32 * FEAT; idx += 1024) {
        int r = idx / FEAT, c = idx % FEAT;
        s1[r][c] = g_feat[(size_t)(i0 + r) * FEAT + c];
        s2[r][c] = g_feat[(size_t)(NW + j0 + r) * FEAT + c];
    }
    __syncthreads();
    int i = i0 + threadIdx.y, j = j0 + threadIdx.x;
    float d = 0.f;
#pragma unroll
    for (int c = 0; c < FEAT; c++) {
        float t = s1[threadIdx.y][c] - s2[threadIdx.x][c];
        d += t * t;
    }
    float p = ex2f(fmaxf(-d * LOG2E, -100.f));
    int s  = i >> 6;
    int l  = (i >> 1) & 31;
    int rp = i & 1;
    int cc = j >> 1;
    int jp = j & 1;
    int t  = cc + l;
    g_Ds[(((size_t)s * D_TPAD + t) * 32 + l) * 4 + rp * 2 + jp] = p;
}

// ---------------- soft-DTW: probability-domain DP, memory ops hoisted off the superstep ----------------
__global__ void __launch_bounds__(32)
softdtw_prob(float* __restrict__ out) {
    const int s = blockIdx.x;
    const int lane = threadIdx.x;
    const int is31 = (lane == 31);
    const int isLast = (s == NSTRIP - 1);
    const int pubp = is31 & !isLast;

    float EA = 0.f, EB = 0.f, carry = 0.f;
    float sh0 = 0.f, sh1 = 0.f;
    int   M = 0, shM = 0;
    if (s == 0 && lane == 0) carry = 1.f;

    const float4* dsp = ((const float4*)g_Ds) + (size_t)s * D_TPAD * 32 + lane;
    float4 dbuf[4];
#pragma unroll
    for (int q = 0; q < 4; ++q) dbuf[q] = __ldg(dsp + (size_t)q * 32);

    const float4* rowprev = g_row4 + (size_t)(s - 1) * 1024;
    float4* rowmine = g_row4 + (size_t)s * 1024;
    int* myflag = &g_flag2[s * 32];
    const int* prevflag = &g_flag2[(s - 1) * 32];
    int flagseen = 0;

    float outE = 1.f; int outM = 0;

    float4 rp[8];
#pragma unroll
    for (int q = 0; q < 8; ++q) rp[q] = make_float4(0.f, 0.f, 0.f, 0.f);

    for (int C = 0; C < SS_CHUNKS; ++C) {
        if (s > 0 && C < 128) {
            const int need = C + 1;
            if (flagseen < need)
                while ((flagseen = ldacq(prevflag)) < need) { }
#pragma unroll
            for (int q = 0; q < 8; ++q) rp[q] = __ldg(&rowprev[C * 8 + q]);
            if (C == 0 && lane == 0) M = (int)rp[0].z;
        }

        float pub0[8], pub1[8]; int pubM[8];

#pragma unroll
        for (int q = 0; q < 8; ++q) {
            const int t = C * 8 + q;
            const int c = t - lane;
            float nE0 = __shfl_up_sync(0xffffffffu, sh0, 1);
            float nE1 = __shfl_up_sync(0xffffffffu, sh1, 1);
            int   nM  = __shfl_up_sync(0xffffffffu, shM, 1);
            if (lane == 0) { nE0 = rp[q].x; nE1 = rp[q].y; nM = (int)rp[q].z; }
            if (c < 0) M = nM;
            int dmm = M - nM;
            dmm = dmm < -126 ? -126 : (dmm > 126 ? 126 : dmm);
            float sc = __uint_as_float((unsigned)(dmm + 127) << 23);
            float FB0 = nE0 * sc;
            float FB1 = nE1 * sc;

            float4 p = dbuf[t & 3];
            dbuf[t & 3] = __ldg(dsp + (size_t)(t + 4) * 32);

            float a0 = p.x * ((carry + FB0) + EA);
            float a1 = p.y * ((FB0 + FB1) + a0);
            float b0 = p.z * ((EB + EA) + a0);
            float b1 = p.w * ((b0 + a1) + a0);

            const int active = (c >= 0) & (c < 1024);

            pub0[q] = b0; pub1[q] = b1; pubM[q] = M;
            outE = (is31 & isLast & active & (c == 1023)) ? b1 : outE;
            outM = (is31 & isLast & active & (c == 1023)) ? M  : outM;

            sh0 = active ? b0 : sh0;
            sh1 = active ? b1 : sh1;
            shM = active ? M  : shM;

            int e = (__float_as_int(b1) >> 23) & 255;
            int doR = active & (e > 0) & (e < 254);
            int dm = doR ? (e - 127) : 0;
            float scR = __uint_as_float((unsigned)(254 - (doR ? e : 127)) << 23);
            EA = (active ? a1 : EA) * scR;
            EB = (active ? b1 : EB) * scR;
            carry = FB1 * scR;
            M = M - dm;
        }

        {
            const int c0 = C * 8 - 31;
#pragma unroll
            for (int q = 0; q < 8; ++q) {
                const int cq = c0 + q;
                stg4_pred(rowmine + cq, pub0[q], pub1[q], (float)pubM[q],
                          pubp & (cq >= 0) & (cq < 1024));
            }
            red_rel_pred(myflag, pubp & (C >= 4));
        }
    }

    stg_pred(out, ((float)outM - lg2f(outE)) * LN2, is31 & isLast);
}

// ---------------- host orchestration ----------------
extern "C" void kernel_launch(void* const* d_in, const int* in_sizes, int n_in,
                              void* d_out, int out_size) {
    const float* x    = (const float*)d_in[0];
    const float* y    = (const float*)d_in[1];
    const float* Wih1 = (const float*)d_in[2];
    const float* Whh1 = (const float*)d_in[3];
    const float* bih1 = (const float*)d_in[4];
    const float* bhh1 = (const float*)d_in[5];
    const float* Wih2 = (const float*)d_in[6];
    const float* Whh2 = (const float*)d_in[7];
    const float* bih2 = (const float*)d_in[8];
    const float* bhh2 = (const float*)d_in[9];
    const float* W1   = (const float*)d_in[10];
    const float* b1   = (const float*)d_in[11];
    float* out = (float*)d_out;

    float *seq, *gi, *h1all, *whT1, *whT2;
    cudaGetSymbolAddress((void**)&seq,   g_seq);
    cudaGetSymbolAddress((void**)&gi,    g_gi);
    cudaGetSymbolAddress((void**)&h1all, g_h1all);
    cudaGetSymbolAddress((void**)&whT1,  g_WhhT1);
    cudaGetSymbolAddress((void**)&whT2,  g_WhhT2);

    const int GRU_SMEM = (32 * HID + 32 * G3) * 4;   // 64 KB
    cudaFuncSetAttribute(gru_layer_kernel,
                         cudaFuncAttributeMaxDynamicSharedMemorySize, GRU_SMEM);

    // 1) prep
    {
        int total = STEPS * BATCH * IN_F;
        prep_kernel<<<(total + 255) / 256, 256>>>(x, y, Whh1, Whh2);
    }

    // 2) layer-1 input gates: seq @ Wih1^T  (K=72)
    sgemm_db<8><<<dim3(G3 / 128, (STEPS * BATCH) / 128), 256>>>(
        seq, Wih1, bih1, gi, STEPS * BATCH, G3, IN_F);

    // 3) layer-1 recurrence
    gru_layer_kernel<<<BATCH / 32, 512, GRU_SMEM>>>(
        gi, (const float4*)whT1, bhh1, h1all, nullptr, nullptr);

    // 4) layer-2 input gates: h1all @ Wih2^T  (K=128)
    sgemm_db<16><<<dim3(G3 / 128, (STEPS * BATCH) / 128), 256>>>(
        h1all, Wih2, bih2, gi, STEPS * BATCH, G3, HID);

    // 5) layer-2 recurrence + fused feature projection
    gru_layer_kernel<<<BATCH / 32, 512, GRU_SMEM>>>(
        gi, (const float4*)whT2, bhh2, nullptr, W1, b1);

    // 6) pairwise distances -> probability domain, skewed block layout
    pairdist_kernel<<<dim3(NW / 32, NW / 32), dim3(32, 32)>>>();

    // 7) soft-DTW probability-domain wavefront
    softdtw_prob<<<NSTRIP, 32>>>(out);
}

// round 9
// speedup vs baseline: 1.1388x; 1.1388x over previous
#include <cuda_runtime.h>
#include <math.h>

#define T_LEN   8196
#define WIN     8
#define STRIDE  4
#define NW      2048
#define BATCH   4096
#define IN_F    72
#define HID     128
#define G3      384
#define FEAT    30
#define STEPS   8
#define LOG2E   1.44269504f
#define LN2     0.693147180559945f

#define NSTRIP  32               // soft-DTW strips of 64 rows
#define SS_CHUNKS 132            // 132 chunks x 8 supersteps = 1056
#define D_TPAD  1064             // superstep dim incl. prefetch pad

// ---------------- static scratch ----------------
__device__ float g_seq  [STEPS * BATCH * IN_F];
__device__ float g_gi   [STEPS * BATCH * G3];
__device__ float g_h1all[STEPS * BATCH * HID];
__device__ float g_feat [BATCH * FEAT];
__device__ float g_Ds   [NSTRIP * D_TPAD * 32 * 4];   // skewed 2x2-block p = 2^(-d*lg2e)
__device__ float g_WhhT1[HID * G3];
__device__ float g_WhhT2[HID * G3];
__device__ float4 g_row4[NSTRIP * 1024];              // handoff: (E_b0, E_b1, M, 0) raw
__device__ int   g_flag2[NSTRIP * 32];                // flags 128B apart

// ---------------- PTX helpers ----------------
__device__ __forceinline__ float ex2f(float x) {
    float r; asm("ex2.approx.ftz.f32 %0, %1;" : "=f"(r) : "f"(x)); return r;
}
__device__ __forceinline__ float lg2f(float x) {
    float r; asm("lg2.approx.ftz.f32 %0, %1;" : "=f"(r) : "f"(x)); return r;
}
__device__ __forceinline__ int ldacq(const int* p) {
    int v; asm volatile("ld.acquire.gpu.global.b32 %0, [%1];" : "=r"(v) : "l"(p) : "memory"); return v;
}

// ---------------- prep ----------------
__global__ void prep_kernel(const float* __restrict__ x, const float* __restrict__ y,
                            const float* __restrict__ Whh1, const float* __restrict__ Whh2) {
    int idx = blockIdx.x * blockDim.x + threadIdx.x;
    const int total = STEPS * BATCH * IN_F;
    if (idx < total) {
        int f = idx % IN_F;
        int b = (idx / IN_F) % BATCH;
        int s = idx / (IN_F * BATCH);
        const float* src = (b < NW) ? x : y;
        int w = b & (NW - 1);
        g_seq[idx] = src[(size_t)f * T_LEN + w * STRIDE + s];
    }
    if (idx < HID * G3) {
        int k = idx / G3, n = idx % G3;
        g_WhhT1[idx] = Whh1[(size_t)n * HID + k];
        g_WhhT2[idx] = Whh2[(size_t)n * HID + k];
    }
    if (idx < NSTRIP) g_flag2[idx * 32] = 0;
}

// ---------------- SGEMM (double-buffered, warp-tiled): C = A@B^T + bias ----------------
template<int BK>
__global__ void __launch_bounds__(256)
sgemm_db(const float* __restrict__ A, const float* __restrict__ Bw,
         const float* __restrict__ bias, float* __restrict__ C,
         int M, int N, int K) {
    constexpr int BM = 128, BN = 128;
    constexpr int PAD = 4;
    constexpr int C4S = BK / 4;
    constexpr int NL  = (BM * BK / 4) / 256;

    __shared__ float As[2][BK][BM + PAD];
    __shared__ float Bs[2][BK][BN + PAD];

    const int tid = threadIdx.x;
    const int rb = blockIdx.y * BM;
    const int cb = blockIdx.x * BN;
    const int warp = tid >> 5, lane = tid & 31;
    const int wr = (warp & 3) * 32;
    const int wc = (warp >> 2) * 64;
    const int lr = ((lane >> 3) & 3) * 8;
    const int lc = (lane & 7) * 8;

    const int nt = K / BK;

    float4 aR[NL], bR[NL];
    int lrow[NL], lcc[NL];
#pragma unroll
    for (int i = 0; i < NL; ++i) {
        int idx = tid + i * 256;
        lrow[i] = idx / C4S;
        lcc[i]  = idx % C4S;
    }

    auto loadT = [&](int t) {
#pragma unroll
        for (int i = 0; i < NL; ++i) {
            aR[i] = *(const float4*)&A[(size_t)(rb + lrow[i]) * K + t * BK + lcc[i] * 4];
            bR[i] = *(const float4*)&Bw[(size_t)(cb + lrow[i]) * K + t * BK + lcc[i] * 4];
        }
    };
    auto storeT = [&](int buf) {
#pragma unroll
        for (int i = 0; i < NL; ++i) {
            As[buf][lcc[i] * 4 + 0][lrow[i]] = aR[i].x;
            As[buf][lcc[i] * 4 + 1][lrow[i]] = aR[i].y;
            As[buf][lcc[i] * 4 + 2][lrow[i]] = aR[i].z;
            As[buf][lcc[i] * 4 + 3][lrow[i]] = aR[i].w;
            Bs[buf][lcc[i] * 4 + 0][lrow[i]] = bR[i].x;
            Bs[buf][lcc[i] * 4 + 1][lrow[i]] = bR[i].y;
            Bs[buf][lcc[i] * 4 + 2][lrow[i]] = bR[i].z;
            Bs[buf][lcc[i] * 4 + 3][lrow[i]] = bR[i].w;
        }
    };

    float acc[8][8];
#pragma unroll
    for (int i = 0; i < 8; i++)
#pragma unroll
        for (int j = 0; j < 8; j++) acc[i][j] = 0.f;

    loadT(0);
    storeT(0);
    __syncthreads();

    for (int t = 0; t < nt; ++t) {
        const int cur = t & 1;
        if (t + 1 < nt) loadT(t + 1);
#pragma unroll
        for (int kk = 0; kk < BK; ++kk) {
            float4 a0 = *(const float4*)&As[cur][kk][wr + lr];
            float4 a1 = *(const float4*)&As[cur][kk][wr + lr + 4];
            float4 b0 = *(const float4*)&Bs[cur][kk][wc + lc];
            float4 b1 = *(const float4*)&Bs[cur][kk][wc + lc + 4];
            float ra[8]  = {a0.x, a0.y, a0.z, a0.w, a1.x, a1.y, a1.z, a1.w};
            float rbv[8] = {b0.x, b0.y, b0.z, b0.w, b1.x, b1.y, b1.z, b1.w};
#pragma unroll
            for (int i = 0; i < 8; i++)
#pragma unroll
                for (int j = 0; j < 8; j++)
                    acc[i][j] += ra[i] * rbv[j];
        }
        if (t + 1 < nt) storeT((t + 1) & 1);
        __syncthreads();
    }

    float bv[8];
#pragma unroll
    for (int j = 0; j < 8; j++) bv[j] = bias[cb + wc + lc + j];
#pragma unroll
    for (int i = 0; i < 8; i++) {
        int row = rb + wr + lr + i;
        float4 o0 = make_float4(acc[i][0] + bv[0], acc[i][1] + bv[1],
                                acc[i][2] + bv[2], acc[i][3] + bv[3]);
        float4 o1 = make_float4(acc[i][4] + bv[4], acc[i][5] + bv[5],
                                acc[i][6] + bv[6], acc[i][7] + bv[7]);
        *(float4*)&C[(size_t)row * N + cb + wc + lc]     = o0;
        *(float4*)&C[(size_t)row * N + cb + wc + lc + 4] = o1;
    }
}

// ---------------- persistent GRU layer (split-K; R3-form inner loop) ----------------
__global__ void __launch_bounds__(512)
gru_layer_kernel(const float* __restrict__ gi,
                 const float4* __restrict__ W4,    // [HID][G3] as float4
                 const float* __restrict__ bhh,
                 float* __restrict__ hall,
                 const float* __restrict__ W1,
                 const float* __restrict__ b1)
{
    extern __shared__ float sraw[];
    float (*hsm)[HID] = (float (*)[HID])sraw;
    float (*psum)[G3] = (float (*)[G3])(sraw + 32 * HID);

    const int tid = threadIdx.x;
    const int kh  = tid >> 8;
    const int gt  = tid & 255;
    const int tr  = gt >> 5;
    const int tc  = gt & 31;
    const int rb  = blockIdx.x * 32;
    const int kbase = kh * 64;
    const bool comb = (kh == 0) ? (tr < 4) : (tr >= 4);

    for (int m = tid; m < 32 * HID; m += 512) sraw[m] = 0.f;
    __syncthreads();

    float bq[3][4];
#pragma unroll
    for (int g = 0; g < 3; ++g) {
        float4 bb = *(const float4*)&bhh[g * HID + tc * 4];
        bq[g][0] = bb.x; bq[g][1] = bb.y; bq[g][2] = bb.z; bq[g][3] = bb.w;
    }

    for (int step = 0; step < STEPS; ++step) {
        float acc[4][3][4];
#pragma unroll
        for (int ii = 0; ii < 4; ++ii)
#pragma unroll
            for (int g = 0; g < 3; ++g)
#pragma unroll
                for (int o = 0; o < 4; ++o) acc[ii][g][o] = 0.f;

#pragma unroll 4
        for (int kk = 0; kk < 64; ++kk) {
            const int k = kbase + kk;
            float a[4];
#pragma unroll
            for (int ii = 0; ii < 4; ++ii) a[ii] = hsm[tr * 4 + ii][k];
#pragma unroll
            for (int g = 0; g < 3; ++g) {
                float4 b = __ldg(&W4[k * 96 + g * 32 + tc]);
#pragma unroll
                for (int ii = 0; ii < 4; ++ii) {
                    acc[ii][g][0] += a[ii] * b.x;
                    acc[ii][g][1] += a[ii] * b.y;
                    acc[ii][g][2] += a[ii] * b.z;
                    acc[ii][g][3] += a[ii] * b.w;
                }
            }
        }
        __syncthreads();

        if (!comb) {
#pragma unroll
            for (int ii = 0; ii < 4; ++ii) {
                const int r = tr * 4 + ii;
#pragma unroll
                for (int g = 0; g < 3; ++g)
                    *(float4*)&psum[r][g * HID + tc * 4] =
                        make_float4(acc[ii][g][0], acc[ii][g][1],
                                    acc[ii][g][2], acc[ii][g][3]);
            }
        }
        __syncthreads();

        if (comb) {
            const size_t rowbase = (size_t)step * BATCH + rb;
#pragma unroll
            for (int ii = 0; ii < 4; ++ii) {
                const int r = tr * 4 + ii;
                const float* gb = gi + (rowbase + r) * G3;
                float4 gr = __ldg((const float4*)(gb + tc * 4));
                float4 gz = __ldg((const float4*)(gb + HID + tc * 4));
                float4 gn = __ldg((const float4*)(gb + 2 * HID + tc * 4));
                float4 p0 = *(const float4*)&psum[r][0 * HID + tc * 4];
                float4 p1 = *(const float4*)&psum[r][1 * HID + tc * 4];
                float4 p2 = *(const float4*)&psum[r][2 * HID + tc * 4];
                float4 ho = *(const float4*)&hsm[r][tc * 4];
                float irv[4] = {gr.x, gr.y, gr.z, gr.w};
                float izv[4] = {gz.x, gz.y, gz.z, gz.w};
                float inv[4] = {gn.x, gn.y, gn.z, gn.w};
                float hv [4] = {ho.x, ho.y, ho.z, ho.w};
                float pr [4] = {p0.x, p0.y, p0.z, p0.w};
                float pz [4] = {p1.x, p1.y, p1.z, p1.w};
                float pn [4] = {p2.x, p2.y, p2.z, p2.w};
                float ov[4];
#pragma unroll
                for (int o = 0; o < 4; ++o) {
                    float hr = acc[ii][0][o] + pr[o] + bq[0][o];
                    float hz = acc[ii][1][o] + pz[o] + bq[1][o];
                    float hn = acc[ii][2][o] + pn[o] + bq[2][o];
                    float rg = 1.f / (1.f + __expf(-(irv[o] + hr)));
                    float zg = 1.f / (1.f + __expf(-(izv[o] + hz)));
                    float ng = tanhf(inv[o] + rg * hn);
                    ov[o] = (1.f - zg) * ng + zg * hv[o];
                }
                float4 hn4 = make_float4(ov[0], ov[1], ov[2], ov[3]);
                *(float4*)&hsm[r][tc * 4] = hn4;
                if (hall)
                    *(float4*)&hall[(rowbase + r) * HID + tc * 4] = hn4;
            }
        }
        __syncthreads();
    }

    if (W1) {
        for (int t = tid; t < 32 * FEAT; t += 512) {
            int r = t / FEAT, o = t % FEAT;
            float s = b1[o];
            const float* w = W1 + (size_t)o * HID;
#pragma unroll 8
            for (int k = 0; k < HID; ++k) s += hsm[r][k] * w[k];
            g_feat[(size_t)(rb + r) * FEAT + o] = s;
        }
    }
}

// ---------------- pairwise: store p = 2^(-d*log2e) in skewed 2x2-block layout ----------------
__global__ void pairdist_kernel() {
    __shared__ float s1[32][31];
    __shared__ float s2[32][31];
    int tid = threadIdx.y * 32 + threadIdx.x;
    int i0 = blockIdx.y * 32, j0 = blockIdx.x * 32;
    for (int idx = tid; idx < 32 * FEAT; idx += 1024) {
        int r = idx / FEAT, c = idx % FEAT;
        s1[r][c] = g_feat[(size_t)(i0 + r) * FEAT + c];
        s2[r][c] = g_feat[(size_t)(NW + j0 + r) * FEAT + c];
    }
    __syncthreads();
    int i = i0 + threadIdx.y, j = j0 + threadIdx.x;
    float d = 0.f;
#pragma unroll
    for (int c = 0; c < FEAT; c++) {
        float t = s1[threadIdx.y][c] - s2[threadIdx.x][c];
        d += t * t;
    }
    float p = ex2f(fmaxf(-d * LOG2E, -100.f));
    int s  = i >> 6;
    int l  = (i >> 1) & 31;
    int rp = i & 1;
    int cc = j >> 1;
    int jp = j & 1;
    int t  = cc + l;
    g_Ds[(((size_t)s * D_TPAD + t) * 32 + l) * 4 + rp * 2 + jp] = p;
}

// ---------------- soft-DTW: warp-specialized (warp0 = DP compute, warp1 = comm) ----------------
// warp0 inner loop has NO global stores / fences / acquires: shfl + FADD/FMUL + __ldg D-prefetch.
// warp1 handles: flag polling (ld.acquire), rowprev prefetch -> smem inbox,
//                smem outbox -> global publish, __threadfence + red flag release.
// Double-buffered inbox/outbox, one __syncthreads per chunk.
__global__ void __launch_bounds__(64)
softdtw_ws(float* __restrict__ out) {
    const int s = blockIdx.x;
    const int tid = threadIdx.x;
    const int warpi = tid >> 5;
    const int lane = tid & 31;

    __shared__ float4 inbox[2][8];
    __shared__ float4 outbox[2][8];

    if (tid < 16) inbox[tid >> 3][tid & 7] = make_float4(0.f, 0.f, 0.f, 0.f);
    __syncthreads();

    if (warpi == 1) {
        // ---------------- comm warp ----------------
        const float4* rowprev = g_row4 + (size_t)(s - 1) * 1024;
        float4* rowmine = g_row4 + (size_t)s * 1024;
        int* myflag = &g_flag2[s * 32];
        const int* prevflag = &g_flag2[(s - 1) * 32];
        const int doIn  = (s > 0);
        const int doOut = (s < NSTRIP - 1);

        // prefill inbox[0] for warp0's chunk 0
        if (doIn && lane < 8) {
            while (ldacq(prevflag) < 1) { }
            inbox[0][lane] = __ldg(&rowprev[lane]);
        }
        __syncthreads();   // matches warp0's pre-loop sync

        for (int I = 0; I <= SS_CHUNKS; ++I) {
            // (a) publish outbox of chunk I-1 (lanes 8-15), computed by warp0 last iteration
            if (lane >= 8 && lane < 16) {
                const int Cp = I - 1;
                if (doOut && Cp >= 0 && Cp < SS_CHUNKS) {
                    const int q = lane - 8;
                    const int cq = Cp * 8 - 31 + q;
                    if (cq >= 0 && cq < 1024)
                        rowmine[cq] = outbox[Cp & 1][q];
                }
            }
            __syncwarp();
            if (lane == 8 && doOut && I >= 5) {      // Cp = I-1 >= 4: same flag algebra as before
                __threadfence();
                asm volatile("red.relaxed.gpu.global.add.u32 [%0], 1;"
                             :: "l"(myflag) : "memory");
            }
            // (b) prefetch rowprev for warp0's chunk I+1 (lanes 0-7)
            if (lane < 8) {
                const int Cn = I + 1;
                if (doIn && Cn < 128) {
                    while (ldacq(prevflag) < Cn + 1) { }
                    inbox[Cn & 1][lane] = __ldg(&rowprev[Cn * 8 + lane]);
                }
            }
            __syncthreads();
        }
    } else {
        // ---------------- compute warp ----------------
        const int is31 = (lane == 31);
        const int isLast = (s == NSTRIP - 1);

        float EA = 0.f, EB = 0.f, carry = 0.f;
        float sh0 = 0.f, sh1 = 0.f;
        int   M = 0, shM = 0;
        if (s == 0 && lane == 0) carry = 1.f;

        const float4* dsp = ((const float4*)g_Ds) + (size_t)s * D_TPAD * 32 + lane;
        float4 dbuf[4];
#pragma unroll
        for (int q = 0; q < 4; ++q) dbuf[q] = __ldg(dsp + (size_t)q * 32);

        float outE = 1.f; int outM = 0;

        __syncthreads();   // inbox[0] ready

        for (int I = 0; I <= SS_CHUNKS; ++I) {
            if (I < SS_CHUNKS) {
                float4 rp[8];
#pragma unroll
                for (int q = 0; q < 8; ++q) rp[q] = inbox[I & 1][q];
                if (I == 0 && s > 0 && lane == 0) M = (int)rp[0].z;

                float pub0[8], pub1[8]; int pubM[8];

#pragma unroll
                for (int q = 0; q < 8; ++q) {
                    const int t = I * 8 + q;
                    const int c = t - lane;
                    float nE0 = __shfl_up_sync(0xffffffffu, sh0, 1);
                    float nE1 = __shfl_up_sync(0xffffffffu, sh1, 1);
                    int   nM  = __shfl_up_sync(0xffffffffu, shM, 1);
                    if (lane == 0) { nE0 = rp[q].x; nE1 = rp[q].y; nM = (int)rp[q].z; }
                    if (c < 0) M = nM;
                    int dmm = M - nM;
                    dmm = dmm < -126 ? -126 : (dmm > 126 ? 126 : dmm);
                    float sc = __uint_as_float((unsigned)(dmm + 127) << 23);
                    float FB0 = nE0 * sc;
                    float FB1 = nE1 * sc;

                    float4 p = dbuf[t & 3];
                    dbuf[t & 3] = __ldg(dsp + (size_t)(t + 4) * 32);

                    float a0 = p.x * ((carry + FB0) + EA);
                    float a1 = p.y * ((FB0 + FB1) + a0);
                    float b0 = p.z * ((EB + EA) + a0);
                    float b1 = p.w * ((b0 + a1) + a0);

                    const int active = (c >= 0) & (c < 1024);

                    pub0[q] = b0; pub1[q] = b1; pubM[q] = M;
                    outE = (is31 & isLast & active & (c == 1023)) ? b1 : outE;
                    outM = (is31 & isLast & active & (c == 1023)) ? M  : outM;

                    sh0 = active ? b0 : sh0;
                    sh1 = active ? b1 : sh1;
                    shM = active ? M  : shM;

                    int e = (__float_as_int(b1) >> 23) & 255;
                    int doR = active & (e > 0) & (e < 254);
                    int dm = doR ? (e - 127) : 0;
                    float scR = __uint_as_float((unsigned)(254 - (doR ? e : 127)) << 23);
                    EA = (active ? a1 : EA) * scR;
                    EB = (active ? b1 : EB) * scR;
                    carry = FB1 * scR;
                    M = M - dm;
                }

                if (is31 && !isLast) {
#pragma unroll
                    for (int q = 0; q < 8; ++q)
                        outbox[I & 1][q] =
                            make_float4(pub0[q], pub1[q], (float)pubM[q], 0.f);
                }
            }
            __syncthreads();
        }

        if (is31 && isLast)
            out[0] = ((float)outM - lg2f(outE)) * LN2;
    }
}

// ---------------- host orchestration ----------------
extern "C" void kernel_launch(void* const* d_in, const int* in_sizes, int n_in,
                              void* d_out, int out_size) {
    const float* x    = (const float*)d_in[0];
    const float* y    = (const float*)d_in[1];
    const float* Wih1 = (const float*)d_in[2];
    const float* Whh1 = (const float*)d_in[3];
    const float* bih1 = (const float*)d_in[4];
    const float* bhh1 = (const float*)d_in[5];
    const float* Wih2 = (const float*)d_in[6];
    const float* Whh2 = (const float*)d_in[7];
    const float* bih2 = (const float*)d_in[8];
    const float* bhh2 = (const float*)d_in[9];
    const float* W1   = (const float*)d_in[10];
    const float* b1   = (const float*)d_in[11];
    float* out = (float*)d_out;

    float *seq, *gi, *h1all, *whT1, *whT2;
    cudaGetSymbolAddress((void**)&seq,   g_seq);
    cudaGetSymbolAddress((void**)&gi,    g_gi);
    cudaGetSymbolAddress((void**)&h1all, g_h1all);
    cudaGetSymbolAddress((void**)&whT1,  g_WhhT1);
    cudaGetSymbolAddress((void**)&whT2,  g_WhhT2);

    const int GRU_SMEM = (32 * HID + 32 * G3) * 4;   // 64 KB
    cudaFuncSetAttribute(gru_layer_kernel,
                         cudaFuncAttributeMaxDynamicSharedMemorySize, GRU_SMEM);

    // 1) prep
    {
        int total = STEPS * BATCH * IN_F;
        prep_kernel<<<(total + 255) / 256, 256>>>(x, y, Whh1, Whh2);
    }

    // 2) layer-1 input gates: seq @ Wih1^T  (K=72)
    sgemm_db<8><<<dim3(G3 / 128, (STEPS * BATCH) / 128), 256>>>(
        seq, Wih1, bih1, gi, STEPS * BATCH, G3, IN_F);

    // 3) layer-1 recurrence
    gru_layer_kernel<<<BATCH / 32, 512, GRU_SMEM>>>(
        gi, (const float4*)whT1, bhh1, h1all, nullptr, nullptr);

    // 4) layer-2 input gates: h1all @ Wih2^T  (K=128)
    sgemm_db<16><<<dim3(G3 / 128, (STEPS * BATCH) / 128), 256>>>(
        h1all, Wih2, bih2, gi, STEPS * BATCH, G3, HID);

    // 5) layer-2 recurrence + fused feature projection
    gru_layer_kernel<<<BATCH / 32, 512, GRU_SMEM>>>(
        gi, (const float4*)whT2, bhh2, nullptr, W1, b1);

    // 6) pairwise distances -> probability domain, skewed block layout
    pairdist_kernel<<<dim3(NW / 32, NW / 32), dim3(32, 32)>>>();

    // 7) soft-DTW warp-specialized wavefront
    softdtw_ws<<<NSTRIP, 64>>>(out);
}

// round 10
// speedup vs baseline: 1.1669x; 1.0247x over previous
#include <cuda_runtime.h>
#include <math.h>

#define T_LEN   8196
#define WIN     8
#define STRIDE  4
#define NW      2048
#define BATCH   4096
#define IN_F    72
#define HID     128
#define G3      384
#define FEAT    30
#define STEPS   8
#define LOG2E   1.44269504f
#define LN2     0.693147180559945f

#define NSTRIP4 16               // strips of 128 rows
#define QCOLS   512              // column quads (4 cols each)
#define SS4_CHUNKS 68            // 68 chunks x 8 supersteps = 544 >= 512+31
#define T4PAD   548              // superstep dim incl. prefetch pad

// ---------------- static scratch ----------------
__device__ float g_seq  [STEPS * BATCH * IN_F];
__device__ float g_gi   [STEPS * BATCH * G3];
__device__ float g_h1all[STEPS * BATCH * HID];
__device__ float g_feat [BATCH * FEAT];
__device__ float g_Ds4  [NSTRIP4 * T4PAD * 32 * 16];  // skewed 4x4-block p = 2^(-d*lg2e), ~18MB
__device__ float g_WhhT1[HID * G3];
__device__ float g_WhhT2[HID * G3];
__device__ float4 g_row8[NSTRIP4 * 1024];             // handoff: per quad 2 slots (E0..E3),(M,-,-,-)
__device__ int   g_flag2[NSTRIP4 * 32];               // flags 128B apart

// ---------------- PTX helpers ----------------
__device__ __forceinline__ float ex2f(float x) {
    float r; asm("ex2.approx.ftz.f32 %0, %1;" : "=f"(r) : "f"(x)); return r;
}
__device__ __forceinline__ float lg2f(float x) {
    float r; asm("lg2.approx.ftz.f32 %0, %1;" : "=f"(r) : "f"(x)); return r;
}
__device__ __forceinline__ int ldacq(const int* p) {
    int v; asm volatile("ld.acquire.gpu.global.b32 %0, [%1];" : "=r"(v) : "l"(p) : "memory"); return v;
}
__device__ __forceinline__ void sts4_pred(unsigned addr, float a, float b, float c, float d, int pred) {
    asm volatile("{\n\t.reg .pred p;\n\tsetp.ne.s32 p, %0, 0;\n\t@p st.shared.v4.f32 [%1], {%2, %3, %4, %5};\n\t}"
                 :: "r"(pred), "r"(addr), "f"(a), "f"(b), "f"(c), "f"(d) : "memory");
}

// ---------------- prep ----------------
__global__ void prep_kernel(const float* __restrict__ x, const float* __restrict__ y,
                            const float* __restrict__ Whh1, const float* __restrict__ Whh2) {
    int idx = blockIdx.x * blockDim.x + threadIdx.x;
    const int total = STEPS * BATCH * IN_F;
    if (idx < total) {
        int f = idx % IN_F;
        int b = (idx / IN_F) % BATCH;
        int s = idx / (IN_F * BATCH);
        const float* src = (b < NW) ? x : y;
        int w = b & (NW - 1);
        g_seq[idx] = src[(size_t)f * T_LEN + w * STRIDE + s];
    }
    if (idx < HID * G3) {
        int k = idx / G3, n = idx % G3;
        g_WhhT1[idx] = Whh1[(size_t)n * HID + k];
        g_WhhT2[idx] = Whh2[(size_t)n * HID + k];
    }
    if (idx < NSTRIP4) g_flag2[idx * 32] = 0;
}

// ---------------- SGEMM (double-buffered, warp-tiled): C = A@B^T + bias ----------------
template<int BK>
__global__ void __launch_bounds__(256)
sgemm_db(const float* __restrict__ A, const float* __restrict__ Bw,
         const float* __restrict__ bias, float* __restrict__ C,
         int M, int N, int K) {
    constexpr int BM = 128, BN = 128;
    constexpr int PAD = 4;
    constexpr int C4S = BK / 4;
    constexpr int NL  = (BM * BK / 4) / 256;

    __shared__ float As[2][BK][BM + PAD];
    __shared__ float Bs[2][BK][BN + PAD];

    const int tid = threadIdx.x;
    const int rb = blockIdx.y * BM;
    const int cb = blockIdx.x * BN;
    const int warp = tid >> 5, lane = tid & 31;
    const int wr = (warp & 3) * 32;
    const int wc = (warp >> 2) * 64;
    const int lr = ((lane >> 3) & 3) * 8;
    const int lc = (lane & 7) * 8;

    const int nt = K / BK;

    float4 aR[NL], bR[NL];
    int lrow[NL], lcc[NL];
#pragma unroll
    for (int i = 0; i < NL; ++i) {
        int idx = tid + i * 256;
        lrow[i] = idx / C4S;
        lcc[i]  = idx % C4S;
    }

    auto loadT = [&](int t) {
#pragma unroll
        for (int i = 0; i < NL; ++i) {
            aR[i] = *(const float4*)&A[(size_t)(rb + lrow[i]) * K + t * BK + lcc[i] * 4];
            bR[i] = *(const float4*)&Bw[(size_t)(cb + lrow[i]) * K + t * BK + lcc[i] * 4];
        }
    };
    auto storeT = [&](int buf) {
#pragma unroll
        for (int i = 0; i < NL; ++i) {
            As[buf][lcc[i] * 4 + 0][lrow[i]] = aR[i].x;
            As[buf][lcc[i] * 4 + 1][lrow[i]] = aR[i].y;
            As[buf][lcc[i] * 4 + 2][lrow[i]] = aR[i].z;
            As[buf][lcc[i] * 4 + 3][lrow[i]] = aR[i].w;
            Bs[buf][lcc[i] * 4 + 0][lrow[i]] = bR[i].x;
            Bs[buf][lcc[i] * 4 + 1][lrow[i]] = bR[i].y;
            Bs[buf][lcc[i] * 4 + 2][lrow[i]] = bR[i].z;
            Bs[buf][lcc[i] * 4 + 3][lrow[i]] = bR[i].w;
        }
    };

    float acc[8][8];
#pragma unroll
    for (int i = 0; i < 8; i++)
#pragma unroll
        for (int j = 0; j < 8; j++) acc[i][j] = 0.f;

    loadT(0);
    storeT(0);
    __syncthreads();

    for (int t = 0; t < nt; ++t) {
        const int cur = t & 1;
        if (t + 1 < nt) loadT(t + 1);
#pragma unroll
        for (int kk = 0; kk < BK; ++kk) {
            float4 a0 = *(const float4*)&As[cur][kk][wr + lr];
            float4 a1 = *(const float4*)&As[cur][kk][wr + lr + 4];
            float4 b0 = *(const float4*)&Bs[cur][kk][wc + lc];
            float4 b1 = *(const float4*)&Bs[cur][kk][wc + lc + 4];
            float ra[8]  = {a0.x, a0.y, a0.z, a0.w, a1.x, a1.y, a1.z, a1.w};
            float rbv[8] = {b0.x, b0.y, b0.z, b0.w, b1.x, b1.y, b1.z, b1.w};
#pragma unroll
            for (int i = 0; i < 8; i++)
#pragma unroll
                for (int j = 0; j < 8; j++)
                    acc[i][j] += ra[i] * rbv[j];
        }
        if (t + 1 < nt) storeT((t + 1) & 1);
        __syncthreads();
    }

    float bv[8];
#pragma unroll
    for (int j = 0; j < 8; j++) bv[j] = bias[cb + wc + lc + j];
#pragma unroll
    for (int i = 0; i < 8; i++) {
        int row = rb + wr + lr + i;
        float4 o0 = make_float4(acc[i][0] + bv[0], acc[i][1] + bv[1],
                                acc[i][2] + bv[2], acc[i][3] + bv[3]);
        float4 o1 = make_float4(acc[i][4] + bv[4], acc[i][5] + bv[5],
                                acc[i][6] + bv[6], acc[i][7] + bv[7]);
        *(float4*)&C[(size_t)row * N + cb + wc + lc]     = o0;
        *(float4*)&C[(size_t)row * N + cb + wc + lc + 4] = o1;
    }
}

// ---------------- persistent GRU layer (split-K; R3-form inner loop) ----------------
__global__ void __launch_bounds__(512)
gru_layer_kernel(const float* __restrict__ gi,
                 const float4* __restrict__ W4,    // [HID][G3] as float4
                 const float* __restrict__ bhh,
                 float* __restrict__ hall,
                 const float* __restrict__ W1,
                 const float* __restrict__ b1)
{
    extern __shared__ float sraw[];
    float (*hsm)[HID] = (float (*)[HID])sraw;
    float (*psum)[G3] = (float (*)[G3])(sraw + 32 * HID);

    const int tid = threadIdx.x;
    const int kh  = tid >> 8;
    const int gt  = tid & 255;
    const int tr  = gt >> 5;
    const int tc  = gt & 31;
    const int rb  = blockIdx.x * 32;
    const int kbase = kh * 64;
    const bool comb = (kh == 0) ? (tr < 4) : (tr >= 4);

    for (int m = tid; m < 32 * HID; m += 512) sraw[m] = 0.f;
    __syncthreads();

    float bq[3][4];
#pragma unroll
    for (int g = 0; g < 3; ++g) {
        float4 bb = *(const float4*)&bhh[g * HID + tc * 4];
        bq[g][0] = bb.x; bq[g][1] = bb.y; bq[g][2] = bb.z; bq[g][3] = bb.w;
    }

    for (int step = 0; step < STEPS; ++step) {
        float acc[4][3][4];
#pragma unroll
        for (int ii = 0; ii < 4; ++ii)
#pragma unroll
            for (int g = 0; g < 3; ++g)
#pragma unroll
                for (int o = 0; o < 4; ++o) acc[ii][g][o] = 0.f;

#pragma unroll 4
        for (int kk = 0; kk < 64; ++kk) {
            const int k = kbase + kk;
            float a[4];
#pragma unroll
            for (int ii = 0; ii < 4; ++ii) a[ii] = hsm[tr * 4 + ii][k];
#pragma unroll
            for (int g = 0; g < 3; ++g) {
                float4 b = __ldg(&W4[k * 96 + g * 32 + tc]);
#pragma unroll
                for (int ii = 0; ii < 4; ++ii) {
                    acc[ii][g][0] += a[ii] * b.x;
                    acc[ii][g][1] += a[ii] * b.y;
                    acc[ii][g][2] += a[ii] * b.z;
                    acc[ii][g][3] += a[ii] * b.w;
                }
            }
        }
        __syncthreads();

        if (!comb) {
#pragma unroll
            for (int ii = 0; ii < 4; ++ii) {
                const int r = tr * 4 + ii;
#pragma unroll
                for (int g = 0; g < 3; ++g)
                    *(float4*)&psum[r][g * HID + tc * 4] =
                        make_float4(acc[ii][g][0], acc[ii][g][1],
                                    acc[ii][g][2], acc[ii][g][3]);
            }
        }
        __syncthreads();

        if (comb) {
            const size_t rowbase = (size_t)step * BATCH + rb;
#pragma unroll
            for (int ii = 0; ii < 4; ++ii) {
                const int r = tr * 4 + ii;
                const float* gb = gi + (rowbase + r) * G3;
                float4 gr = __ldg((const float4*)(gb + tc * 4));
                float4 gz = __ldg((const float4*)(gb + HID + tc * 4));
                float4 gn = __ldg((const float4*)(gb + 2 * HID + tc * 4));
                float4 p0 = *(const float4*)&psum[r][0 * HID + tc * 4];
                float4 p1 = *(const float4*)&psum[r][1 * HID + tc * 4];
                float4 p2 = *(const float4*)&psum[r][2 * HID + tc * 4];
                float4 ho = *(const float4*)&hsm[r][tc * 4];
                float irv[4] = {gr.x, gr.y, gr.z, gr.w};
                float izv[4] = {gz.x, gz.y, gz.z, gz.w};
                float inv[4] = {gn.x, gn.y, gn.z, gn.w};
                float hv [4] = {ho.x, ho.y, ho.z, ho.w};
                float pr [4] = {p0.x, p0.y, p0.z, p0.w};
                float pz [4] = {p1.x, p1.y, p1.z, p1.w};
                float pn [4] = {p2.x, p2.y, p2.z, p2.w};
                float ov[4];
#pragma unroll
                for (int o = 0; o < 4; ++o) {
                    float hr = acc[ii][0][o] + pr[o] + bq[0][o];
                    float hz = acc[ii][1][o] + pz[o] + bq[1][o];
                    float hn = acc[ii][2][o] + pn[o] + bq[2][o];
                    float rg = 1.f / (1.f + __expf(-(irv[o] + hr)));
                    float zg = 1.f / (1.f + __expf(-(izv[o] + hz)));
                    float ng = tanhf(inv[o] + rg * hn);
                    ov[o] = (1.f - zg) * ng + zg * hv[o];
                }
                float4 hn4 = make_float4(ov[0], ov[1], ov[2], ov[3]);
                *(float4*)&hsm[r][tc * 4] = hn4;
                if (hall)
                    *(float4*)&hall[(rowbase + r) * HID + tc * 4] = hn4;
            }
        }
        __syncthreads();
    }

    if (W1) {
        for (int t = tid; t < 32 * FEAT; t += 512) {
            int r = t / FEAT, o = t % FEAT;
            float s = b1[o];
            const float* w = W1 + (size_t)o * HID;
#pragma unroll 8
            for (int k = 0; k < HID; ++k) s += hsm[r][k] * w[k];
            g_feat[(size_t)(rb + r) * FEAT + o] = s;
        }
    }
}

// ---------------- pairwise: store p = 2^(-d*log2e) in skewed 4x4-block layout ----------------
// element (s, t, l, ri, rj): strip s=i>>7, lane l=(i>>2)&31, ri=i&3, quad cq=j>>2, rj=j&3, t=cq+l
__global__ void pairdist_kernel() {
    __shared__ float s1[32][31];
    __shared__ float s2[32][31];
    int tid = threadIdx.y * 32 + threadIdx.x;
    int i0 = blockIdx.y * 32, j0 = blockIdx.x * 32;
    for (int idx = tid; idx < 32 * FEAT; idx += 1024) {
        int r = idx / FEAT, c = idx % FEAT;
        s1[r][c] = g_feat[(size_t)(i0 + r) * FEAT + c];
        s2[r][c] = g_feat[(size_t)(NW + j0 + r) * FEAT + c];
    }
    __syncthreads();
    int i = i0 + threadIdx.y, j = j0 + threadIdx.x;
    float d = 0.f;
#pragma unroll
    for (int c = 0; c < FEAT; c++) {
        float t = s1[threadIdx.y][c] - s2[threadIdx.x][c];
        d += t * t;
    }
    float p = ex2f(fmaxf(-d * LOG2E, -100.f));
    int s  = i >> 7;
    int l  = (i >> 2) & 31;
    int ri = i & 3;
    int cq = j >> 2;
    int rj = j & 3;
    int t  = cq + l;
    g_Ds4[((((size_t)s * T4PAD + t) * 32 + l) * 4 + ri) * 4 + rj] = p;
}

// ---------------- soft-DTW: 4x4 blocks/lane, warp-specialized (warp0 compute, warp1 comm) ----------------
// 16 strips of 128 rows; lane l owns rows 4l..4l+3; superstep t -> col quad c = t - l.
// Prob-domain: E' = p*(diag+up+left); per-lane exponent M, renorm keyed on block corner.
// Handoff records per quad: slot0 = (E of bottom row cols 4c..4c+3, raw), slot1 = (M,-,-,-).
__global__ void __launch_bounds__(64)
softdtw_ws4(float* __restrict__ out) {
    const int s = blockIdx.x;
    const int tid = threadIdx.x;
    const int warpi = tid >> 5;
    const int lane = tid & 31;

    __shared__ float4 inbox[2][16];
    __shared__ float4 outbox[2][16];

    if (tid < 32) inbox[tid >> 4][tid & 15] = make_float4(0.f, 0.f, 0.f, 0.f);
    __syncthreads();

    if (warpi == 1) {
        // ---------------- comm warp ----------------
        const float4* rowprev8 = g_row8 + (size_t)(s - 1) * 1024;
        float4* rowmine8 = g_row8 + (size_t)s * 1024;
        int* myflag = &g_flag2[s * 32];
        const int* prevflag = &g_flag2[(s - 1) * 32];
        const int doIn  = (s > 0);
        const int doOut = (s < NSTRIP4 - 1);

        if (doIn && lane < 16) {
            while (ldacq(prevflag) < 1) { }
            inbox[0][lane] = __ldg(&rowprev8[lane]);
        }
        __syncthreads();

        for (int I = 0; I <= SS4_CHUNKS; ++I) {
            if (lane >= 16) {
                const int Cp = I - 1;
                if (doOut && Cp >= 0) {
                    int kk = lane - 16;
                    int q = kk >> 1, h = kk & 1;
                    int cq = Cp * 8 - 31 + q;
                    if (cq >= 0 && cq < QCOLS)
                        rowmine8[cq * 2 + h] = outbox[Cp & 1][kk];
                }
            }
            __syncwarp();
            if (lane == 16 && doOut && I >= 5) {
                __threadfence();
                asm volatile("red.relaxed.gpu.global.add.u32 [%0], 1;"
                             :: "l"(myflag) : "memory");
            }
            if (lane < 16) {
                const int Cn = I + 1;
                if (doIn && Cn < 64) {
                    while (ldacq(prevflag) < Cn + 1) { }
                    inbox[Cn & 1][lane] = __ldg(&rowprev8[Cn * 16 + lane]);
                }
            }
            __syncthreads();
        }
    } else {
        // ---------------- compute warp ----------------
        const int is31 = (lane == 31);
        const int isLast = (s == NSTRIP4 - 1);
        const int pubp = is31 & !isLast;

        float L0 = 0.f, L1 = 0.f, L2 = 0.f, L3 = 0.f;   // own left col E (scaled, domain M)
        float carry = 0.f;                               // diag E (scaled)
        float sh0 = 0.f, sh1 = 0.f, sh2 = 0.f, sh3 = 0.f; // raw bottom-row E for shfl
        int   M = 0, shM = 0;
        if (s == 0 && lane == 0) carry = 1.f;            // seed R(-1,-1)=0

        const float4* dsp = ((const float4*)g_Ds4) + (size_t)s * T4PAD * 128 + lane * 4;
        float4 db[2][4];
#pragma unroll
        for (int ri = 0; ri < 4; ++ri) {
            db[0][ri] = __ldg(dsp + ri);
            db[1][ri] = __ldg(dsp + 128 + ri);
        }

        unsigned obase = (unsigned)__cvta_generic_to_shared(&outbox[0][0]);

        float outE = 1.f; int outM = 0;

        __syncthreads();   // inbox[0] ready

        for (int I = 0; I <= SS4_CHUNKS; ++I) {
            if (I < SS4_CHUNKS) {
#pragma unroll
                for (int q = 0; q < 8; ++q) {
                    const int t = I * 8 + q;
                    const int c = t - lane;

                    float4 rE = inbox[I & 1][2 * q];
                    float  rM = inbox[I & 1][2 * q + 1].x;
                    if (I == 0 && q == 0 && s > 0 && lane == 0) M = (int)rM;

                    float nB0 = __shfl_up_sync(0xffffffffu, sh0, 1);
                    float nB1 = __shfl_up_sync(0xffffffffu, sh1, 1);
                    float nB2 = __shfl_up_sync(0xffffffffu, sh2, 1);
                    float nB3 = __shfl_up_sync(0xffffffffu, sh3, 1);
                    int   nM  = __shfl_up_sync(0xffffffffu, shM, 1);
                    if (lane == 0) { nB0 = rE.x; nB1 = rE.y; nB2 = rE.z; nB3 = rE.w; nM = (int)rM; }
                    if (c < 0) M = nM;
                    int dmm = M - nM;
                    dmm = dmm < -126 ? -126 : (dmm > 126 ? 126 : dmm);
                    float sc = __uint_as_float((unsigned)(dmm + 127) << 23);
                    float U0 = nB0 * sc, U1 = nB1 * sc, U2 = nB2 * sc, U3 = nB3 * sc;

                    float4 p0 = db[q & 1][0], p1 = db[q & 1][1];
                    float4 p2 = db[q & 1][2], p3 = db[q & 1][3];
                    {   // prefetch superstep t+2
                        const float4* np = dsp + (size_t)(t + 2) * 128;
                        db[q & 1][0] = __ldg(np);
                        db[q & 1][1] = __ldg(np + 1);
                        db[q & 1][2] = __ldg(np + 2);
                        db[q & 1][3] = __ldg(np + 3);
                    }

                    float e00 = p0.x * ((carry + U0) + L0);
                    float e01 = p0.y * ((U0 + U1) + e00);
                    float e02 = p0.z * ((U1 + U2) + e01);
                    float e03 = p0.w * ((U2 + U3) + e02);
                    float e10 = p1.x * ((L0 + e00) + L1);
                    float e11 = p1.y * ((e00 + e01) + e10);
                    float e12 = p1.z * ((e01 + e02) + e11);
                    float e13 = p1.w * ((e02 + e03) + e12);
                    float e20 = p2.x * ((L1 + e10) + L2);
                    float e21 = p2.y * ((e10 + e11) + e20);
                    float e22 = p2.z * ((e11 + e12) + e21);
                    float e23 = p2.w * ((e12 + e13) + e22);
                    float e30 = p3.x * ((L2 + e20) + L3);
                    float e31 = p3.y * ((e20 + e21) + e30);
                    float e32 = p3.z * ((e21 + e22) + e31);
                    float e33 = p3.w * ((e22 + e23) + e32);

                    const int active = (c >= 0) & (c < QCOLS);

                    // outbox record (raw, pre-renorm); comm bounds-checks cq so inactive garbage never published
                    sts4_pred(obase + (unsigned)(((I & 1) * 16 + 2 * q) * 16),
                              e30, e31, e32, e33, pubp);
                    sts4_pred(obase + (unsigned)(((I & 1) * 16 + 2 * q + 1) * 16),
                              (float)M, 0.f, 0.f, 0.f, pubp);

                    outE = (is31 & isLast & active & (c == QCOLS - 1)) ? e33 : outE;
                    outM = (is31 & isLast & active & (c == QCOLS - 1)) ? M   : outM;

                    sh0 = active ? e30 : sh0;
                    sh1 = active ? e31 : sh1;
                    sh2 = active ? e32 : sh2;
                    sh3 = active ? e33 : sh3;
                    shM = active ? M   : shM;

                    int eb = (__float_as_int(e33) >> 23) & 255;
                    int doR = active & (eb > 0) & (eb < 254);
                    int dm = doR ? (eb - 127) : 0;
                    float scR = __uint_as_float((unsigned)(254 - (doR ? eb : 127)) << 23);
                    L0 = (active ? e03 : L0) * scR;
                    L1 = (active ? e13 : L1) * scR;
                    L2 = (active ? e23 : L2) * scR;
                    L3 = (active ? e33 : L3) * scR;
                    carry = U3 * scR;
                    M = M - dm;
                }
            }
            __syncthreads();
        }

        if (is31 && isLast)
            out[0] = ((float)outM - lg2f(outE)) * LN2;
    }
}

// ---------------- host orchestration ----------------
extern "C" void kernel_launch(void* const* d_in, const int* in_sizes, int n_in,
                              void* d_out, int out_size) {
    const float* x    = (const float*)d_in[0];
    const float* y    = (const float*)d_in[1];
    const float* Wih1 = (const float*)d_in[2];
    const float* Whh1 = (const float*)d_in[3];
    const float* bih1 = (const float*)d_in[4];
    const float* bhh1 = (const float*)d_in[5];
    const float* Wih2 = (const float*)d_in[6];
    const float* Whh2 = (const float*)d_in[7];
    const float* bih2 = (const float*)d_in[8];
    const float* bhh2 = (const float*)d_in[9];
    const float* W1   = (const float*)d_in[10];
    const float* b1   = (const float*)d_in[11];
    float* out = (float*)d_out;

    float *seq, *gi, *h1all, *whT1, *whT2;
    cudaGetSymbolAddress((void**)&seq,   g_seq);
    cudaGetSymbolAddress((void**)&gi,    g_gi);
    cudaGetSymbolAddress((void**)&h1all, g_h1all);
    cudaGetSymbolAddress((void**)&whT1,  g_WhhT1);
    cudaGetSymbolAddress((void**)&whT2,  g_WhhT2);

    const int GRU_SMEM = (32 * HID + 32 * G3) * 4;   // 64 KB
    cudaFuncSetAttribute(gru_layer_kernel,
                         cudaFuncAttributeMaxDynamicSharedMemorySize, GRU_SMEM);

    // 1) prep
    {
        int total = STEPS * BATCH * IN_F;
        prep_kernel<<<(total + 255) / 256, 256>>>(x, y, Whh1, Whh2);
    }

    // 2) layer-1 input gates: seq @ Wih1^T  (K=72)
    sgemm_db<8><<<dim3(G3 / 128, (STEPS * BATCH) / 128), 256>>>(
        seq, Wih1, bih1, gi, STEPS * BATCH, G3, IN_F);

    // 3) layer-1 recurrence
    gru_layer_kernel<<<BATCH / 32, 512, GRU_SMEM>>>(
        gi, (const float4*)whT1, bhh1, h1all, nullptr, nullptr);

    // 4) layer-2 input gates: h1all @ Wih2^T  (K=128)
    sgemm_db<16><<<dim3(G3 / 128, (STEPS * BATCH) / 128), 256>>>(
        h1all, Wih2, bih2, gi, STEPS * BATCH, G3, HID);

    // 5) layer-2 recurrence + fused feature projection
    gru_layer_kernel<<<BATCH / 32, 512, GRU_SMEM>>>(
        gi, (const float4*)whT2, bhh2, nullptr, W1, b1);

    // 6) pairwise distances -> probability domain, skewed 4x4-block layout
    pairdist_kernel<<<dim3(NW / 32, NW / 32), dim3(32, 32)>>>();

    // 7) soft-DTW 4x4-block warp-specialized wavefront
    softdtw_ws4<<<NSTRIP4, 64>>>(out);
}

// round 11
// speedup vs baseline: 1.5217x; 1.3040x over previous
#include <cuda_runtime.h>
#include <math.h>

#define T_LEN   8196
#define WIN     8
#define STRIDE  4
#define NW      2048
#define BATCH   4096
#define IN_F    72
#define HID     128
#define G3      384
#define FEAT    30
#define STEPS   8
#define LOG2E   1.44269504f
#define LN2     0.693147180559945f

#define NSTRIP4 16               // strips of 128 rows
#define QCOLS   512              // column quads (4 cols each)
#define SS4_CHUNKS 68            // 68 chunks x 8 supersteps = 544 >= 512+31
#define T4PAD   548              // superstep dim incl. pad

// ---------------- static scratch ----------------
__device__ float g_seq  [STEPS * BATCH * IN_F];
__device__ float g_gi   [STEPS * BATCH * G3];
__device__ float g_h1all[STEPS * BATCH * HID];
__device__ float g_feat [BATCH * FEAT];
__device__ float g_Ds4  [NSTRIP4 * T4PAD * 32 * 16];  // [s][t][ri][lane] float4(rj), p = 2^(-d*lg2e)
__device__ float g_WhhT1[HID * G3];
__device__ float g_WhhT2[HID * G3];
__device__ float4 g_row8[NSTRIP4 * 1024];             // handoff: per quad 2 slots (E0..E3),(M,-,-,-)
__device__ int   g_flag2[NSTRIP4 * 32];               // flags 128B apart

// ---------------- PTX helpers ----------------
__device__ __forceinline__ float ex2f(float x) {
    float r; asm("ex2.approx.ftz.f32 %0, %1;" : "=f"(r) : "f"(x)); return r;
}
__device__ __forceinline__ float lg2f(float x) {
    float r; asm("lg2.approx.ftz.f32 %0, %1;" : "=f"(r) : "f"(x)); return r;
}
__device__ __forceinline__ int ldacq(const int* p) {
    int v; asm volatile("ld.acquire.gpu.global.b32 %0, [%1];" : "=r"(v) : "l"(p) : "memory"); return v;
}
__device__ __forceinline__ void sts4_pred(unsigned addr, float a, float b, float c, float d, int pred) {
    asm volatile("{\n\t.reg .pred p;\n\tsetp.ne.s32 p, %0, 0;\n\t@p st.shared.v4.f32 [%1], {%2, %3, %4, %5};\n\t}"
                 :: "r"(pred), "r"(addr), "f"(a), "f"(b), "f"(c), "f"(d) : "memory");
}
__device__ __forceinline__ void cpasync16(unsigned saddr, const void* gaddr) {
    asm volatile("cp.async.cg.shared.global [%0], [%1], 16;" :: "r"(saddr), "l"(gaddr));
}

// ---------------- prep ----------------
__global__ void prep_kernel(const float* __restrict__ x, const float* __restrict__ y,
                            const float* __restrict__ Whh1, const float* __restrict__ Whh2) {
    int idx = blockIdx.x * blockDim.x + threadIdx.x;
    const int total = STEPS * BATCH * IN_F;
    if (idx < total) {
        int f = idx % IN_F;
        int b = (idx / IN_F) % BATCH;
        int s = idx / (IN_F * BATCH);
        const float* src = (b < NW) ? x : y;
        int w = b & (NW - 1);
        g_seq[idx] = src[(size_t)f * T_LEN + w * STRIDE + s];
    }
    if (idx < HID * G3) {
        int k = idx / G3, n = idx % G3;
        g_WhhT1[idx] = Whh1[(size_t)n * HID + k];
        g_WhhT2[idx] = Whh2[(size_t)n * HID + k];
    }
    if (idx < NSTRIP4) g_flag2[idx * 32] = 0;
}

// ---------------- SGEMM (double-buffered, warp-tiled): C = A@B^T + bias ----------------
template<int BK>
__global__ void __launch_bounds__(256)
sgemm_db(const float* __restrict__ A, const float* __restrict__ Bw,
         const float* __restrict__ bias, float* __restrict__ C,
         int M, int N, int K) {
    constexpr int BM = 128, BN = 128;
    constexpr int PAD = 4;
    constexpr int C4S = BK / 4;
    constexpr int NL  = (BM * BK / 4) / 256;

    __shared__ float As[2][BK][BM + PAD];
    __shared__ float Bs[2][BK][BN + PAD];

    const int tid = threadIdx.x;
    const int rb = blockIdx.y * BM;
    const int cb = blockIdx.x * BN;
    const int warp = tid >> 5, lane = tid & 31;
    const int wr = (warp & 3) * 32;
    const int wc = (warp >> 2) * 64;
    const int lr = ((lane >> 3) & 3) * 8;
    const int lc = (lane & 7) * 8;

    const int nt = K / BK;

    float4 aR[NL], bR[NL];
    int lrow[NL], lcc[NL];
#pragma unroll
    for (int i = 0; i < NL; ++i) {
        int idx = tid + i * 256;
        lrow[i] = idx / C4S;
        lcc[i]  = idx % C4S;
    }

    auto loadT = [&](int t) {
#pragma unroll
        for (int i = 0; i < NL; ++i) {
            aR[i] = *(const float4*)&A[(size_t)(rb + lrow[i]) * K + t * BK + lcc[i] * 4];
            bR[i] = *(const float4*)&Bw[(size_t)(cb + lrow[i]) * K + t * BK + lcc[i] * 4];
        }
    };
    auto storeT = [&](int buf) {
#pragma unroll
        for (int i = 0; i < NL; ++i) {
            As[buf][lcc[i] * 4 + 0][lrow[i]] = aR[i].x;
            As[buf][lcc[i] * 4 + 1][lrow[i]] = aR[i].y;
            As[buf][lcc[i] * 4 + 2][lrow[i]] = aR[i].z;
            As[buf][lcc[i] * 4 + 3][lrow[i]] = aR[i].w;
            Bs[buf][lcc[i] * 4 + 0][lrow[i]] = bR[i].x;
            Bs[buf][lcc[i] * 4 + 1][lrow[i]] = bR[i].y;
            Bs[buf][lcc[i] * 4 + 2][lrow[i]] = bR[i].z;
            Bs[buf][lcc[i] * 4 + 3][lrow[i]] = bR[i].w;
        }
    };

    float acc[8][8];
#pragma unroll
    for (int i = 0; i < 8; i++)
#pragma unroll
        for (int j = 0; j < 8; j++) acc[i][j] = 0.f;

    loadT(0);
    storeT(0);
    __syncthreads();

    for (int t = 0; t < nt; ++t) {
        const int cur = t & 1;
        if (t + 1 < nt) loadT(t + 1);
#pragma unroll
        for (int kk = 0; kk < BK; ++kk) {
            float4 a0 = *(const float4*)&As[cur][kk][wr + lr];
            float4 a1 = *(const float4*)&As[cur][kk][wr + lr + 4];
            float4 b0 = *(const float4*)&Bs[cur][kk][wc + lc];
            float4 b1 = *(const float4*)&Bs[cur][kk][wc + lc + 4];
            float ra[8]  = {a0.x, a0.y, a0.z, a0.w, a1.x, a1.y, a1.z, a1.w};
            float rbv[8] = {b0.x, b0.y, b0.z, b0.w, b1.x, b1.y, b1.z, b1.w};
#pragma unroll
            for (int i = 0; i < 8; i++)
#pragma unroll
                for (int j = 0; j < 8; j++)
                    acc[i][j] += ra[i] * rbv[j];
        }
        if (t + 1 < nt) storeT((t + 1) & 1);
        __syncthreads();
    }

    float bv[8];
#pragma unroll
    for (int j = 0; j < 8; j++) bv[j] = bias[cb + wc + lc + j];
#pragma unroll
    for (int i = 0; i < 8; i++) {
        int row = rb + wr + lr + i;
        float4 o0 = make_float4(acc[i][0] + bv[0], acc[i][1] + bv[1],
                                acc[i][2] + bv[2], acc[i][3] + bv[3]);
        float4 o1 = make_float4(acc[i][4] + bv[4], acc[i][5] + bv[5],
                                acc[i][6] + bv[6], acc[i][7] + bv[7]);
        *(float4*)&C[(size_t)row * N + cb + wc + lc]     = o0;
        *(float4*)&C[(size_t)row * N + cb + wc + lc + 4] = o1;
    }
}

// ---------------- persistent GRU layer (split-K; R3-form inner loop) ----------------
__global__ void __launch_bounds__(512)
gru_layer_kernel(const float* __restrict__ gi,
                 const float4* __restrict__ W4,    // [HID][G3] as float4
                 const float* __restrict__ bhh,
                 float* __restrict__ hall,
                 const float* __restrict__ W1,
                 const float* __restrict__ b1)
{
    extern __shared__ float sraw[];
    float (*hsm)[HID] = (float (*)[HID])sraw;
    float (*psum)[G3] = (float (*)[G3])(sraw + 32 * HID);

    const int tid = threadIdx.x;
    const int kh  = tid >> 8;
    const int gt  = tid & 255;
    const int tr  = gt >> 5;
    const int tc  = gt & 31;
    const int rb  = blockIdx.x * 32;
    const int kbase = kh * 64;
    const bool comb = (kh == 0) ? (tr < 4) : (tr >= 4);

    for (int m = tid; m < 32 * HID; m += 512) sraw[m] = 0.f;
    __syncthreads();

    float bq[3][4];
#pragma unroll
    for (int g = 0; g < 3; ++g) {
        float4 bb = *(const float4*)&bhh[g * HID + tc * 4];
        bq[g][0] = bb.x; bq[g][1] = bb.y; bq[g][2] = bb.z; bq[g][3] = bb.w;
    }

    for (int step = 0; step < STEPS; ++step) {
        float acc[4][3][4];
#pragma unroll
        for (int ii = 0; ii < 4; ++ii)
#pragma unroll
            for (int g = 0; g < 3; ++g)
#pragma unroll
                for (int o = 0; o < 4; ++o) acc[ii][g][o] = 0.f;

#pragma unroll 4
        for (int kk = 0; kk < 64; ++kk) {
            const int k = kbase + kk;
            float a[4];
#pragma unroll
            for (int ii = 0; ii < 4; ++ii) a[ii] = hsm[tr * 4 + ii][k];
#pragma unroll
            for (int g = 0; g < 3; ++g) {
                float4 b = __ldg(&W4[k * 96 + g * 32 + tc]);
#pragma unroll
                for (int ii = 0; ii < 4; ++ii) {
                    acc[ii][g][0] += a[ii] * b.x;
                    acc[ii][g][1] += a[ii] * b.y;
                    acc[ii][g][2] += a[ii] * b.z;
                    acc[ii][g][3] += a[ii] * b.w;
                }
            }
        }
        __syncthreads();

        if (!comb) {
#pragma unroll
            for (int ii = 0; ii < 4; ++ii) {
                const int r = tr * 4 + ii;
#pragma unroll
                for (int g = 0; g < 3; ++g)
                    *(float4*)&psum[r][g * HID + tc * 4] =
                        make_float4(acc[ii][g][0], acc[ii][g][1],
                                    acc[ii][g][2], acc[ii][g][3]);
            }
        }
        __syncthreads();

        if (comb) {
            const size_t rowbase = (size_t)step * BATCH + rb;
#pragma unroll
            for (int ii = 0; ii < 4; ++ii) {
                const int r = tr * 4 + ii;
                const float* gb = gi + (rowbase + r) * G3;
                float4 gr = __ldg((const float4*)(gb + tc * 4));
                float4 gz = __ldg((const float4*)(gb + HID + tc * 4));
                float4 gn = __ldg((const float4*)(gb + 2 * HID + tc * 4));
                float4 p0 = *(const float4*)&psum[r][0 * HID + tc * 4];
                float4 p1 = *(const float4*)&psum[r][1 * HID + tc * 4];
                float4 p2 = *(const float4*)&psum[r][2 * HID + tc * 4];
                float4 ho = *(const float4*)&hsm[r][tc * 4];
                float irv[4] = {gr.x, gr.y, gr.z, gr.w};
                float izv[4] = {gz.x, gz.y, gz.z, gz.w};
                float inv[4] = {gn.x, gn.y, gn.z, gn.w};
                float hv [4] = {ho.x, ho.y, ho.z, ho.w};
                float pr [4] = {p0.x, p0.y, p0.z, p0.w};
                float pz [4] = {p1.x, p1.y, p1.z, p1.w};
                float pn [4] = {p2.x, p2.y, p2.z, p2.w};
                float ov[4];
#pragma unroll
                for (int o = 0; o < 4; ++o) {
                    float hr = acc[ii][0][o] + pr[o] + bq[0][o];
                    float hz = acc[ii][1][o] + pz[o] + bq[1][o];
                    float hn = acc[ii][2][o] + pn[o] + bq[2][o];
                    float rg = 1.f / (1.f + __expf(-(irv[o] + hr)));
                    float zg = 1.f / (1.f + __expf(-(izv[o] + hz)));
                    float ng = tanhf(inv[o] + rg * hn);
                    ov[o] = (1.f - zg) * ng + zg * hv[o];
                }
                float4 hn4 = make_float4(ov[0], ov[1], ov[2], ov[3]);
                *(float4*)&hsm[r][tc * 4] = hn4;
                if (hall)
                    *(float4*)&hall[(rowbase + r) * HID + tc * 4] = hn4;
            }
        }
        __syncthreads();
    }

    if (W1) {
        for (int t = tid; t < 32 * FEAT; t += 512) {
            int r = t / FEAT, o = t % FEAT;
            float s = b1[o];
            const float* w = W1 + (size_t)o * HID;
#pragma unroll 8
            for (int k = 0; k < HID; ++k) s += hsm[r][k] * w[k];
            g_feat[(size_t)(rb + r) * FEAT + o] = s;
        }
    }
}

// ---------------- pairwise: p = 2^(-d*lg2e), layout [s][t][ri][lane] float4(rj) ----------------
__global__ void pairdist_kernel() {
    __shared__ float s1[32][31];
    __shared__ float s2[32][31];
    int tid = threadIdx.y * 32 + threadIdx.x;
    int i0 = blockIdx.y * 32, j0 = blockIdx.x * 32;
    for (int idx = tid; idx < 32 * FEAT; idx += 1024) {
        int r = idx / FEAT, c = idx % FEAT;
        s1[r][c] = g_feat[(size_t)(i0 + r) * FEAT + c];
        s2[r][c] = g_feat[(size_t)(NW + j0 + r) * FEAT + c];
    }
    __syncthreads();
    int i = i0 + threadIdx.y, j = j0 + threadIdx.x;
    float d = 0.f;
#pragma unroll
    for (int c = 0; c < FEAT; c++) {
        float t = s1[threadIdx.y][c] - s2[threadIdx.x][c];
        d += t * t;
    }
    float p = ex2f(fmaxf(-d * LOG2E, -100.f));
    int s  = i >> 7;
    int l  = (i >> 2) & 31;
    int ri = i & 3;
    int cq = j >> 2;
    int rj = j & 3;
    int t  = cq + l;
    g_Ds4[((((size_t)s * T4PAD + t) * 4 + ri) * 32 + l) * 4 + rj] = p;
}

// ---------------- soft-DTW: 4x4 blocks/lane, fully warp-specialized ----------------
// warp0 = pure DP compute: shfl + FADD/FMUL + LDS only (ZERO global loads/stores).
// warp1 = comm: stages D chunks into smem via cp.async (double-buffered, 1 chunk ahead),
//         handles inter-strip flag/row protocol.
__global__ void __launch_bounds__(64)
softdtw_ws4(float* __restrict__ out) {
    const int s = blockIdx.x;
    const int tid = threadIdx.x;
    const int warpi = tid >> 5;
    const int lane = tid & 31;

    __shared__ float4 Dbuf[2][8][4][32];   // [buf][q][ri][lane], 16KB per buf
    __shared__ float4 inbox[2][16];
    __shared__ float4 outbox[2][16];

    if (tid < 32) inbox[tid >> 4][tid & 15] = make_float4(0.f, 0.f, 0.f, 0.f);
    __syncthreads();   // sync A

    if (warpi == 1) {
        // ---------------- comm warp ----------------
        const float4* rowprev8 = g_row8 + (size_t)(s - 1) * 1024;
        float4* rowmine8 = g_row8 + (size_t)s * 1024;
        int* myflag = &g_flag2[s * 32];
        const int* prevflag = &g_flag2[(s - 1) * 32];
        const int doIn  = (s > 0);
        const int doOut = (s < NSTRIP4 - 1);

        const float4* dsrc = ((const float4*)g_Ds4) + (size_t)s * T4PAD * 128;
        unsigned dbase = (unsigned)__cvta_generic_to_shared(&Dbuf[0][0][0][0]);

        auto stageD = [&](int CC) {   // stage chunk CC into Dbuf[CC&1] (linear 1024 float4)
            const float4* g = dsrc + (size_t)CC * 1024;
            unsigned sb = dbase + (unsigned)((CC & 1) * 16384);
#pragma unroll
            for (int k = 0; k < 32; ++k) {
                int u = k * 32 + lane;
                cpasync16(sb + (unsigned)(u * 16), g + u);
            }
            asm volatile("cp.async.commit_group;" ::: "memory");
        };

        // prologue: stage chunk 0, prefill inbox[0]
        stageD(0);
        if (doIn && lane < 16) {
            while (ldacq(prevflag) < 1) { }
            inbox[0][lane] = __ldg(&rowprev8[lane]);
        }
        asm volatile("cp.async.wait_group 0;" ::: "memory");
        __syncthreads();   // sync B

        for (int I = 0; I <= SS4_CHUNKS; ++I) {
            // publish outbox of chunk I-1
            if (lane >= 16) {
                const int Cp = I - 1;
                if (doOut && Cp >= 0) {
                    int kk = lane - 16;
                    int q = kk >> 1, h = kk & 1;
                    int cq = Cp * 8 - 31 + q;
                    if (cq >= 0 && cq < QCOLS)
                        rowmine8[cq * 2 + h] = outbox[Cp & 1][kk];
                }
            }
            __syncwarp();
            if (lane == 16 && doOut && I >= 5) {
                __threadfence();
                asm volatile("red.relaxed.gpu.global.add.u32 [%0], 1;"
                             :: "l"(myflag) : "memory");
            }
            // stage D for chunk I+1
            if (I + 1 < SS4_CHUNKS) stageD(I + 1);
            // inbox prefetch for chunk I+1
            if (lane < 16) {
                const int Cn = I + 1;
                if (doIn && Cn < 64) {
                    while (ldacq(prevflag) < Cn + 1) { }
                    inbox[Cn & 1][lane] = __ldg(&rowprev8[Cn * 16 + lane]);
                }
            }
            asm volatile("cp.async.wait_group 0;" ::: "memory");
            __syncthreads();
        }
    } else {
        // ---------------- compute warp (no global memory ops in the loop) ----------------
        const int is31 = (lane == 31);
        const int isLast = (s == NSTRIP4 - 1);
        const int pubp = is31 & !isLast;

        float L0 = 0.f, L1 = 0.f, L2 = 0.f, L3 = 0.f;
        float carry = 0.f;
        float sh0 = 0.f, sh1 = 0.f, sh2 = 0.f, sh3 = 0.f;
        int   M = 0, shM = 0;
        if (s == 0 && lane == 0) carry = 1.f;

        unsigned obase = (unsigned)__cvta_generic_to_shared(&outbox[0][0]);

        float outE = 1.f; int outM = 0;

        __syncthreads();   // sync B (Dbuf[0], inbox[0] ready)

        for (int I = 0; I <= SS4_CHUNKS; ++I) {
            if (I < SS4_CHUNKS) {
#pragma unroll
                for (int q = 0; q < 8; ++q) {
                    const int t = I * 8 + q;
                    const int c = t - lane;

                    const float4* Dq = &Dbuf[I & 1][q][0][lane];
                    float4 p0 = Dq[0];
                    float4 p1 = Dq[32];
                    float4 p2 = Dq[64];
                    float4 p3 = Dq[96];

                    float4 rE = inbox[I & 1][2 * q];
                    float  rM = inbox[I & 1][2 * q + 1].x;
                    if (I == 0 && q == 0 && s > 0 && lane == 0) M = (int)rM;

                    float nB0 = __shfl_up_sync(0xffffffffu, sh0, 1);
                    float nB1 = __shfl_up_sync(0xffffffffu, sh1, 1);
                    float nB2 = __shfl_up_sync(0xffffffffu, sh2, 1);
                    float nB3 = __shfl_up_sync(0xffffffffu, sh3, 1);
                    int   nM  = __shfl_up_sync(0xffffffffu, shM, 1);
                    if (lane == 0) { nB0 = rE.x; nB1 = rE.y; nB2 = rE.z; nB3 = rE.w; nM = (int)rM; }
                    if (c < 0) M = nM;
                    int dmm = M - nM;
                    dmm = dmm < -126 ? -126 : (dmm > 126 ? 126 : dmm);
                    float sc = __uint_as_float((unsigned)(dmm + 127) << 23);
                    float U0 = nB0 * sc, U1 = nB1 * sc, U2 = nB2 * sc, U3 = nB3 * sc;

                    float e00 = p0.x * ((carry + U0) + L0);
                    float e01 = p0.y * ((U0 + U1) + e00);
                    float e02 = p0.z * ((U1 + U2) + e01);
                    float e03 = p0.w * ((U2 + U3) + e02);
                    float e10 = p1.x * ((L0 + e00) + L1);
                    float e11 = p1.y * ((e00 + e01) + e10);
                    float e12 = p1.z * ((e01 + e02) + e11);
                    float e13 = p1.w * ((e02 + e03) + e12);
                    float e20 = p2.x * ((L1 + e10) + L2);
                    float e21 = p2.y * ((e10 + e11) + e20);
                    float e22 = p2.z * ((e11 + e12) + e21);
                    float e23 = p2.w * ((e12 + e13) + e22);
                    float e30 = p3.x * ((L2 + e20) + L3);
                    float e31 = p3.y * ((e20 + e21) + e30);
                    float e32 = p3.z * ((e21 + e22) + e31);
                    float e33 = p3.w * ((e22 + e23) + e32);

                    const int active = (c >= 0) & (c < QCOLS);

                    sts4_pred(obase + (unsigned)(((I & 1) * 16 + 2 * q) * 16),
                              e30, e31, e32, e33, pubp);
                    sts4_pred(obase + (unsigned)(((I & 1) * 16 + 2 * q + 1) * 16),
                              (float)M, 0.f, 0.f, 0.f, pubp);

                    outE = (is31 & isLast & active & (c == QCOLS - 1)) ? e33 : outE;
                    outM = (is31 & isLast & active & (c == QCOLS - 1)) ? M   : outM;

                    sh0 = active ? e30 : sh0;
                    sh1 = active ? e31 : sh1;
                    sh2 = active ? e32 : sh2;
                    sh3 = active ? e33 : sh3;
                    shM = active ? M   : shM;

                    int eb = (__float_as_int(e33) >> 23) & 255;
                    int doR = active & (eb > 0) & (eb < 254);
                    int dm = doR ? (eb - 127) : 0;
                    float scR = __uint_as_float((unsigned)(254 - (doR ? eb : 127)) << 23);
                    L0 = (active ? e03 : L0) * scR;
                    L1 = (active ? e13 : L1) * scR;
                    L2 = (active ? e23 : L2) * scR;
                    L3 = (active ? e33 : L3) * scR;
                    carry = U3 * scR;
                    M = M - dm;
                }
            }
            __syncthreads();
        }

        if (is31 && isLast)
            out[0] = ((float)outM - lg2f(outE)) * LN2;
    }
}

// ---------------- host orchestration ----------------
extern "C" void kernel_launch(void* const* d_in, const int* in_sizes, int n_in,
                              void* d_out, int out_size) {
    const float* x    = (const float*)d_in[0];
    const float* y    = (const float*)d_in[1];
    const float* Wih1 = (const float*)d_in[2];
    const float* Whh1 = (const float*)d_in[3];
    const float* bih1 = (const float*)d_in[4];
    const float* bhh1 = (const float*)d_in[5];
    const float* Wih2 = (const float*)d_in[6];
    const float* Whh2 = (const float*)d_in[7];
    const float* bih2 = (const float*)d_in[8];
    const float* bhh2 = (const float*)d_in[9];
    const float* W1   = (const float*)d_in[10];
    const float* b1   = (const float*)d_in[11];
    float* out = (float*)d_out;

    float *seq, *gi, *h1all, *whT1, *whT2;
    cudaGetSymbolAddress((void**)&seq,   g_seq);
    cudaGetSymbolAddress((void**)&gi,    g_gi);
    cudaGetSymbolAddress((void**)&h1all, g_h1all);
    cudaGetSymbolAddress((void**)&whT1,  g_WhhT1);
    cudaGetSymbolAddress((void**)&whT2,  g_WhhT2);

    const int GRU_SMEM = (32 * HID + 32 * G3) * 4;   // 64 KB
    cudaFuncSetAttribute(gru_layer_kernel,
                         cudaFuncAttributeMaxDynamicSharedMemorySize, GRU_SMEM);

    // 1) prep
    {
        int total = STEPS * BATCH * IN_F;
        prep_kernel<<<(total + 255) / 256, 256>>>(x, y, Whh1, Whh2);
    }

    // 2) layer-1 input gates: seq @ Wih1^T  (K=72)
    sgemm_db<8><<<dim3(G3 / 128, (STEPS * BATCH) / 128), 256>>>(
        seq, Wih1, bih1, gi, STEPS * BATCH, G3, IN_F);

    // 3) layer-1 recurrence
    gru_layer_kernel<<<BATCH / 32, 512, GRU_SMEM>>>(
        gi, (const float4*)whT1, bhh1, h1all, nullptr, nullptr);

    // 4) layer-2 input gates: h1all @ Wih2^T  (K=128)
    sgemm_db<16><<<dim3(G3 / 128, (STEPS * BATCH) / 128), 256>>>(
        h1all, Wih2, bih2, gi, STEPS * BATCH, G3, HID);

    // 5) layer-2 recurrence + fused feature projection
    gru_layer_kernel<<<BATCH / 32, 512, GRU_SMEM>>>(
        gi, (const float4*)whT2, bhh2, nullptr, W1, b1);

    // 6) pairwise distances -> probability domain, staged layout
    pairdist_kernel<<<dim3(NW / 32, NW / 32), dim3(32, 32)>>>();

    // 7) soft-DTW warp-specialized wavefront, smem-staged D
    softdtw_ws4<<<NSTRIP4, 64>>>(out);
}

// round 12
// speedup vs baseline: 1.5638x; 1.0277x over previous
#include <cuda_runtime.h>
#include <math.h>

#define T_LEN   8196
#define WIN     8
#define STRIDE  4
#define NW      2048
#define BATCH   4096
#define IN_F    72
#define HID     128
#define G3      384
#define FEAT    30
#define STEPS   8
#define LOG2E   1.44269504f
#define LN2     0.693147180559945f

#define NSTRIP4 16               // strips of 128 rows
#define QCOLS   512              // column quads (4 cols each)
#define SS4_CHUNKS 68            // 68 chunks x 8 supersteps = 544 >= 512+31
#define T4PAD   548              // superstep dim incl. pad

// ---------------- static scratch ----------------
__device__ float g_seq  [STEPS * BATCH * IN_F];
__device__ float g_gi   [STEPS * BATCH * G3];
__device__ float g_h1all[STEPS * BATCH * HID];
__device__ float g_feat [BATCH * FEAT];
__device__ float g_Ds4  [NSTRIP4 * T4PAD * 32 * 16];  // [s][t][ri][lane] float4(rj), p = 2^(-d*lg2e)
__device__ float g_WhhT1[HID * G3];
__device__ float g_WhhT2[HID * G3];
__device__ float4 g_row8[NSTRIP4 * 1024];             // handoff: per quad 2 slots (E0..E3),(M,-,-,-)
__device__ int   g_flag2[NSTRIP4 * 32];               // flags 128B apart

// ---------------- PTX helpers ----------------
__device__ __forceinline__ float ex2f(float x) {
    float r; asm("ex2.approx.ftz.f32 %0, %1;" : "=f"(r) : "f"(x)); return r;
}
__device__ __forceinline__ float lg2f(float x) {
    float r; asm("lg2.approx.ftz.f32 %0, %1;" : "=f"(r) : "f"(x)); return r;
}
__device__ __forceinline__ int ldacq(const int* p) {
    int v; asm volatile("ld.acquire.gpu.global.b32 %0, [%1];" : "=r"(v) : "l"(p) : "memory"); return v;
}
__device__ __forceinline__ void sts4_pred(unsigned addr, float a, float b, float c, float d, int pred) {
    asm volatile("{\n\t.reg .pred p;\n\tsetp.ne.s32 p, %0, 0;\n\t@p st.shared.v4.f32 [%1], {%2, %3, %4, %5};\n\t}"
                 :: "r"(pred), "r"(addr), "f"(a), "f"(b), "f"(c), "f"(d) : "memory");
}
__device__ __forceinline__ void cpasync16(unsigned saddr, const void* gaddr) {
    asm volatile("cp.async.cg.shared.global [%0], [%1], 16;" :: "r"(saddr), "l"(gaddr));
}

// ---------------- prep ----------------
__global__ void prep_kernel(const float* __restrict__ x, const float* __restrict__ y,
                            const float* __restrict__ Whh1, const float* __restrict__ Whh2) {
    int idx = blockIdx.x * blockDim.x + threadIdx.x;
    const int total = STEPS * BATCH * IN_F;
    if (idx < total) {
        int f = idx % IN_F;
        int b = (idx / IN_F) % BATCH;
        int s = idx / (IN_F * BATCH);
        const float* src = (b < NW) ? x : y;
        int w = b & (NW - 1);
        g_seq[idx] = src[(size_t)f * T_LEN + w * STRIDE + s];
    }
    if (idx < HID * G3) {
        int k = idx / G3, n = idx % G3;
        g_WhhT1[idx] = Whh1[(size_t)n * HID + k];
        g_WhhT2[idx] = Whh2[(size_t)n * HID + k];
    }
    if (idx < NSTRIP4) g_flag2[idx * 32] = 0;
}

// ---------------- SGEMM (double-buffered, warp-tiled): C = A@B^T + bias ----------------
template<int BK>
__global__ void __launch_bounds__(256)
sgemm_db(const float* __restrict__ A, const float* __restrict__ Bw,
         const float* __restrict__ bias, float* __restrict__ C,
         int M, int N, int K) {
    constexpr int BM = 128, BN = 128;
    constexpr int PAD = 4;
    constexpr int C4S = BK / 4;
    constexpr int NL  = (BM * BK / 4) / 256;

    __shared__ float As[2][BK][BM + PAD];
    __shared__ float Bs[2][BK][BN + PAD];

    const int tid = threadIdx.x;
    const int rb = blockIdx.y * BM;
    const int cb = blockIdx.x * BN;
    const int warp = tid >> 5, lane = tid & 31;
    const int wr = (warp & 3) * 32;
    const int wc = (warp >> 2) * 64;
    const int lr = ((lane >> 3) & 3) * 8;
    const int lc = (lane & 7) * 8;

    const int nt = K / BK;

    float4 aR[NL], bR[NL];
    int lrow[NL], lcc[NL];
#pragma unroll
    for (int i = 0; i < NL; ++i) {
        int idx = tid + i * 256;
        lrow[i] = idx / C4S;
        lcc[i]  = idx % C4S;
    }

    auto loadT = [&](int t) {
#pragma unroll
        for (int i = 0; i < NL; ++i) {
            aR[i] = *(const float4*)&A[(size_t)(rb + lrow[i]) * K + t * BK + lcc[i] * 4];
            bR[i] = *(const float4*)&Bw[(size_t)(cb + lrow[i]) * K + t * BK + lcc[i] * 4];
        }
    };
    auto storeT = [&](int buf) {
#pragma unroll
        for (int i = 0; i < NL; ++i) {
            As[buf][lcc[i] * 4 + 0][lrow[i]] = aR[i].x;
            As[buf][lcc[i] * 4 + 1][lrow[i]] = aR[i].y;
            As[buf][lcc[i] * 4 + 2][lrow[i]] = aR[i].z;
            As[buf][lcc[i] * 4 + 3][lrow[i]] = aR[i].w;
            Bs[buf][lcc[i] * 4 + 0][lrow[i]] = bR[i].x;
            Bs[buf][lcc[i] * 4 + 1][lrow[i]] = bR[i].y;
            Bs[buf][lcc[i] * 4 + 2][lrow[i]] = bR[i].z;
            Bs[buf][lcc[i] * 4 + 3][lrow[i]] = bR[i].w;
        }
    };

    float acc[8][8];
#pragma unroll
    for (int i = 0; i < 8; i++)
#pragma unroll
        for (int j = 0; j < 8; j++) acc[i][j] = 0.f;

    loadT(0);
    storeT(0);
    __syncthreads();

    for (int t = 0; t < nt; ++t) {
        const int cur = t & 1;
        if (t + 1 < nt) loadT(t + 1);
#pragma unroll
        for (int kk = 0; kk < BK; ++kk) {
            float4 a0 = *(const float4*)&As[cur][kk][wr + lr];
            float4 a1 = *(const float4*)&As[cur][kk][wr + lr + 4];
            float4 b0 = *(const float4*)&Bs[cur][kk][wc + lc];
            float4 b1 = *(const float4*)&Bs[cur][kk][wc + lc + 4];
            float ra[8]  = {a0.x, a0.y, a0.z, a0.w, a1.x, a1.y, a1.z, a1.w};
            float rbv[8] = {b0.x, b0.y, b0.z, b0.w, b1.x, b1.y, b1.z, b1.w};
#pragma unroll
            for (int i = 0; i < 8; i++)
#pragma unroll
                for (int j = 0; j < 8; j++)
                    acc[i][j] += ra[i] * rbv[j];
        }
        if (t + 1 < nt) storeT((t + 1) & 1);
        __syncthreads();
    }

    float bv[8];
#pragma unroll
    for (int j = 0; j < 8; j++) bv[j] = bias[cb + wc + lc + j];
#pragma unroll
    for (int i = 0; i < 8; i++) {
        int row = rb + wr + lr + i;
        float4 o0 = make_float4(acc[i][0] + bv[0], acc[i][1] + bv[1],
                                acc[i][2] + bv[2], acc[i][3] + bv[3]);
        float4 o1 = make_float4(acc[i][4] + bv[4], acc[i][5] + bv[5],
                                acc[i][6] + bv[6], acc[i][7] + bv[7]);
        *(float4*)&C[(size_t)row * N + cb + wc + lc]     = o0;
        *(float4*)&C[(size_t)row * N + cb + wc + lc + 4] = o1;
    }
}

// ---------------- persistent GRU layer (split-K; vectorized hsm loads, 2 syncs/step) ----------------
__global__ void __launch_bounds__(512)
gru_layer_kernel(const float* __restrict__ gi,
                 const float4* __restrict__ W4,    // [HID][G3] as float4
                 const float* __restrict__ bhh,
                 float* __restrict__ hall,
                 const float* __restrict__ W1,
                 const float* __restrict__ b1)
{
    extern __shared__ float sraw[];
    float (*hsm)[HID] = (float (*)[HID])sraw;
    float (*psum)[G3] = (float (*)[G3])(sraw + 32 * HID);

    const int tid = threadIdx.x;
    const int kh  = tid >> 8;
    const int gt  = tid & 255;
    const int tr  = gt >> 5;
    const int tc  = gt & 31;
    const int rb  = blockIdx.x * 32;
    const int kbase = kh * 64;
    const bool comb = (kh == 0) ? (tr < 4) : (tr >= 4);

    for (int m = tid; m < 32 * HID; m += 512) sraw[m] = 0.f;
    __syncthreads();

    float bq[3][4];
#pragma unroll
    for (int g = 0; g < 3; ++g) {
        float4 bb = *(const float4*)&bhh[g * HID + tc * 4];
        bq[g][0] = bb.x; bq[g][1] = bb.y; bq[g][2] = bb.z; bq[g][3] = bb.w;
    }

    for (int step = 0; step < STEPS; ++step) {
        float acc[4][3][4];
#pragma unroll
        for (int ii = 0; ii < 4; ++ii)
#pragma unroll
            for (int g = 0; g < 3; ++g)
#pragma unroll
                for (int o = 0; o < 4; ++o) acc[ii][g][o] = 0.f;

#pragma unroll 2
        for (int kk4 = 0; kk4 < 64; kk4 += 4) {
            const int k0 = kbase + kk4;
            float a_[4][4];
#pragma unroll
            for (int ii = 0; ii < 4; ++ii) {
                float4 a4 = *(const float4*)&hsm[tr * 4 + ii][k0];   // broadcast LDS.128
                a_[ii][0] = a4.x; a_[ii][1] = a4.y; a_[ii][2] = a4.z; a_[ii][3] = a4.w;
            }
#pragma unroll
            for (int j = 0; j < 4; ++j) {
#pragma unroll
                for (int g = 0; g < 3; ++g) {
                    float4 b = __ldg(&W4[(k0 + j) * 96 + g * 32 + tc]);
#pragma unroll
                    for (int ii = 0; ii < 4; ++ii) {
                        acc[ii][g][0] += a_[ii][j] * b.x;
                        acc[ii][g][1] += a_[ii][j] * b.y;
                        acc[ii][g][2] += a_[ii][j] * b.z;
                        acc[ii][g][3] += a_[ii][j] * b.w;
                    }
                }
            }
        }

        if (!comb) {   // psum region disjoint from hsm: no sync needed before this
#pragma unroll
            for (int ii = 0; ii < 4; ++ii) {
                const int r = tr * 4 + ii;
#pragma unroll
                for (int g = 0; g < 3; ++g)
                    *(float4*)&psum[r][g * HID + tc * 4] =
                        make_float4(acc[ii][g][0], acc[ii][g][1],
                                    acc[ii][g][2], acc[ii][g][3]);
            }
        }
        __syncthreads();   // GEMM hsm reads done + psum published

        if (comb) {
            const size_t rowbase = (size_t)step * BATCH + rb;
#pragma unroll
            for (int ii = 0; ii < 4; ++ii) {
                const int r = tr * 4 + ii;
                const float* gb = gi + (rowbase + r) * G3;
                float4 gr = __ldg((const float4*)(gb + tc * 4));
                float4 gz = __ldg((const float4*)(gb + HID + tc * 4));
                float4 gn = __ldg((const float4*)(gb + 2 * HID + tc * 4));
                float4 p0 = *(const float4*)&psum[r][0 * HID + tc * 4];
                float4 p1 = *(const float4*)&psum[r][1 * HID + tc * 4];
                float4 p2 = *(const float4*)&psum[r][2 * HID + tc * 4];
                float4 ho = *(const float4*)&hsm[r][tc * 4];
                float irv[4] = {gr.x, gr.y, gr.z, gr.w};
                float izv[4] = {gz.x, gz.y, gz.z, gz.w};
                float inv[4] = {gn.x, gn.y, gn.z, gn.w};
                float hv [4] = {ho.x, ho.y, ho.z, ho.w};
                float pr [4] = {p0.x, p0.y, p0.z, p0.w};
                float pz [4] = {p1.x, p1.y, p1.z, p1.w};
                float pn [4] = {p2.x, p2.y, p2.z, p2.w};
                float ov[4];
#pragma unroll
                for (int o = 0; o < 4; ++o) {
                    float hr = acc[ii][0][o] + pr[o] + bq[0][o];
                    float hz = acc[ii][1][o] + pz[o] + bq[1][o];
                    float hn = acc[ii][2][o] + pn[o] + bq[2][o];
                    float rg = 1.f / (1.f + __expf(-(irv[o] + hr)));
                    float zg = 1.f / (1.f + __expf(-(izv[o] + hz)));
                    float ng = tanhf(inv[o] + rg * hn);
                    ov[o] = (1.f - zg) * ng + zg * hv[o];
                }
                float4 hn4 = make_float4(ov[0], ov[1], ov[2], ov[3]);
                *(float4*)&hsm[r][tc * 4] = hn4;
                if (hall)
                    *(float4*)&hall[(rowbase + r) * HID + tc * 4] = hn4;
            }
        }
        __syncthreads();   // hsm updated before next step's GEMM
    }

    if (W1) {
        for (int t = tid; t < 32 * FEAT; t += 512) {
            int r = t / FEAT, o = t % FEAT;
            float s = b1[o];
            const float* w = W1 + (size_t)o * HID;
#pragma unroll 8
            for (int k = 0; k < HID; ++k) s += hsm[r][k] * w[k];
            g_feat[(size_t)(rb + r) * FEAT + o] = s;
        }
    }
}

// ---------------- pairwise: p = 2^(-d*lg2e), layout [s][t][ri][lane] float4(rj) ----------------
__global__ void pairdist_kernel() {
    __shared__ float s1[32][31];
    __shared__ float s2[32][31];
    __shared__ float dtile[32][33];
    int tid = threadIdx.y * 32 + threadIdx.x;
    int i0 = blockIdx.y * 32, j0 = blockIdx.x * 32;
    for (int idx = tid; idx < 32 * FEAT; idx += 1024) {
        int r = idx / FEAT, c = idx % FEAT;
        s1[r][c] = g_feat[(size_t)(i0 + r) * FEAT + c];
        s2[r][c] = g_feat[(size_t)(NW + j0 + r) * FEAT + c];
    }
    __syncthreads();
    {
        float d = 0.f;
#pragma unroll
        for (int c = 0; c < FEAT; c++) {
            float t = s1[threadIdx.y][c] - s2[threadIdx.x][c];
            d += t * t;
        }
        dtile[threadIdx.y][threadIdx.x] = ex2f(fmaxf(-d * LOG2E, -100.f));
    }
    __syncthreads();
    // vectorized output: 256 float4 stores
    if (tid < 256) {
        int ri  = tid & 3;
        int cq8 = (tid >> 2) & 7;
        int lq  = (tid >> 5) & 7;
        int row = lq * 4 + ri;
        float4 v = make_float4(dtile[row][cq8 * 4 + 0], dtile[row][cq8 * 4 + 1],
                               dtile[row][cq8 * 4 + 2], dtile[row][cq8 * 4 + 3]);
        int i = i0 + row;
        int s = i >> 7;
        int l = (i >> 2) & 31;
        int cq = (j0 >> 2) + cq8;
        int t = cq + l;
        *(float4*)&g_Ds4[((((size_t)s * T4PAD + t) * 4 + ri) * 32 + l) * 4] = v;
    }
}

// ---------------- soft-DTW: 4x4 blocks/lane, warp-specialized, 4-deep D staging ----------------
__global__ void __launch_bounds__(64)
softdtw_ws4(float* __restrict__ out) {
    extern __shared__ char sdtw[];
    float4* Dbufp = (float4*)sdtw;                              // [4][1024] = 64KB
    float4 (*inbox)[16]  = (float4 (*)[16])(sdtw + 65536);      // [2][16]
    float4 (*outbox)[16] = (float4 (*)[16])(sdtw + 65536 + 512);

    const int s = blockIdx.x;
    const int tid = threadIdx.x;
    const int warpi = tid >> 5;
    const int lane = tid & 31;

    if (tid < 32) inbox[tid >> 4][tid & 15] = make_float4(0.f, 0.f, 0.f, 0.f);
    __syncthreads();   // sync A

    if (warpi == 1) {
        // ---------------- comm warp ----------------
        const float4* rowprev8 = g_row8 + (size_t)(s - 1) * 1024;
        float4* rowmine8 = g_row8 + (size_t)s * 1024;
        int* myflag = &g_flag2[s * 32];
        const int* prevflag = &g_flag2[(s - 1) * 32];
        const int doIn  = (s > 0);
        const int doOut = (s < NSTRIP4 - 1);

        const float4* dsrc = ((const float4*)g_Ds4) + (size_t)s * T4PAD * 128;
        unsigned dbase = (unsigned)__cvta_generic_to_shared(Dbufp);

        auto stageD = [&](int CC) {   // chunk CC -> Dbuf[CC&3] (linear 1024 float4)
            const float4* g = dsrc + (size_t)CC * 1024;
            unsigned sb = dbase + (unsigned)((CC & 3) * 16384);
#pragma unroll
            for (int k = 0; k < 32; ++k) {
                int u = k * 32 + lane;
                cpasync16(sb + (unsigned)(u * 16), g + u);
            }
            asm volatile("cp.async.commit_group;" ::: "memory");
        };

        // prologue: stage chunks 0..2, prefill inbox[0]; chunk 0 must be done
        stageD(0); stageD(1); stageD(2);
        if (doIn && lane < 16) {
            while (ldacq(prevflag) < 1) { }
            inbox[0][lane] = __ldg(&rowprev8[lane]);
        }
        asm volatile("cp.async.wait_group 2;" ::: "memory");
        __syncthreads();   // sync B

        for (int I = 0; I <= SS4_CHUNKS; ++I) {
            if (lane >= 16) {
                const int Cp = I - 1;
                if (doOut && Cp >= 0) {
                    int kk = lane - 16;
                    int q = kk >> 1, h = kk & 1;
                    int cq = Cp * 8 - 31 + q;
                    if (cq >= 0 && cq < QCOLS)
                        rowmine8[cq * 2 + h] = outbox[Cp & 1][kk];
                }
            }
            __syncwarp();
            if (lane == 16 && doOut && I >= 5) {
                __threadfence();
                asm volatile("red.relaxed.gpu.global.add.u32 [%0], 1;"
                             :: "l"(myflag) : "memory");
            }
            if (I + 3 < SS4_CHUNKS) stageD(I + 3);
            if (lane < 16) {
                const int Cn = I + 1;
                if (doIn && Cn < 64) {
                    while (ldacq(prevflag) < Cn + 1) { }
                    inbox[Cn & 1][lane] = __ldg(&rowprev8[Cn * 16 + lane]);
                }
            }
            asm volatile("cp.async.wait_group 2;" ::: "memory");   // chunk I+1 complete
            __syncthreads();
        }
    } else {
        // ---------------- compute warp (no global memory ops in the loop) ----------------
        const int is31 = (lane == 31);
        const int isLast = (s == NSTRIP4 - 1);
        const int pubp = is31 & !isLast;

        float L0 = 0.f, L1 = 0.f, L2 = 0.f, L3 = 0.f;
        float carry = 0.f;
        float sh0 = 0.f, sh1 = 0.f, sh2 = 0.f, sh3 = 0.f;
        int   M = 0, shM = 0;
        if (s == 0 && lane == 0) carry = 1.f;

        unsigned obase = (unsigned)__cvta_generic_to_shared(&outbox[0][0]);

        float outE = 1.f; int outM = 0;

        __syncthreads();   // sync B (Dbuf[0..2], inbox[0] staged)

        for (int I = 0; I <= SS4_CHUNKS; ++I) {
            if (I < SS4_CHUNKS) {
#pragma unroll
                for (int q = 0; q < 8; ++q) {
                    const int c = I * 8 + q - lane;

                    const float4* Dq = Dbufp + (I & 3) * 1024 + q * 128 + lane;
                    float4 p0 = Dq[0];
                    float4 p1 = Dq[32];
                    float4 p2 = Dq[64];
                    float4 p3 = Dq[96];

                    float4 rE = inbox[I & 1][2 * q];
                    float  rM = inbox[I & 1][2 * q + 1].x;
                    if (I == 0 && q == 0 && s > 0 && lane == 0) M = (int)rM;

                    float nB0 = __shfl_up_sync(0xffffffffu, sh0, 1);
                    float nB1 = __shfl_up_sync(0xffffffffu, sh1, 1);
                    float nB2 = __shfl_up_sync(0xffffffffu, sh2, 1);
                    float nB3 = __shfl_up_sync(0xffffffffu, sh3, 1);
                    int   nM  = __shfl_up_sync(0xffffffffu, shM, 1);
                    if (lane == 0) { nB0 = rE.x; nB1 = rE.y; nB2 = rE.z; nB3 = rE.w; nM = (int)rM; }
                    if (c < 0) M = nM;
                    int dmm = M - nM;
                    dmm = dmm < -126 ? -126 : (dmm > 126 ? 126 : dmm);
                    float sc = __uint_as_float((unsigned)(dmm + 127) << 23);
                    float U0 = nB0 * sc, U1 = nB1 * sc, U2 = nB2 * sc, U3 = nB3 * sc;

                    float e00 = p0.x * ((carry + U0) + L0);
                    float e01 = p0.y * ((U0 + U1) + e00);
                    float e02 = p0.z * ((U1 + U2) + e01);
                    float e03 = p0.w * ((U2 + U3) + e02);
                    float e10 = p1.x * ((L0 + e00) + L1);
                    float e11 = p1.y * ((e00 + e01) + e10);
                    float e12 = p1.z * ((e01 + e02) + e11);
                    float e13 = p1.w * ((e02 + e03) + e12);
                    float e20 = p2.x * ((L1 + e10) + L2);
                    float e21 = p2.y * ((e10 + e11) + e20);
                    float e22 = p2.z * ((e11 + e12) + e21);
                    float e23 = p2.w * ((e12 + e13) + e22);
                    float e30 = p3.x * ((L2 + e20) + L3);
                    float e31 = p3.y * ((e20 + e21) + e30);
                    float e32 = p3.z * ((e21 + e22) + e31);
                    float e33 = p3.w * ((e22 + e23) + e32);

                    const int active = (c >= 0) & (c < QCOLS);

                    sts4_pred(obase + (unsigned)(((I & 1) * 16 + 2 * q) * 16),
                              e30, e31, e32, e33, pubp);
                    sts4_pred(obase + (unsigned)(((I & 1) * 16 + 2 * q + 1) * 16),
                              (float)M, 0.f, 0.f, 0.f, pubp);

                    outE = (is31 & isLast & active & (c == QCOLS - 1)) ? e33 : outE;
                    outM = (is31 & isLast & active & (c == QCOLS - 1)) ? M   : outM;

                    sh0 = active ? e30 : sh0;
                    sh1 = active ? e31 : sh1;
                    sh2 = active ? e32 : sh2;
                    sh3 = active ? e33 : sh3;
                    shM = active ? M   : shM;

                    int eb = (__float_as_int(e33) >> 23) & 255;
                    int doR = active & (eb > 0) & (eb < 254);
                    int dm = doR ? (eb - 127) : 0;
                    float scR = __uint_as_float((unsigned)(254 - (doR ? eb : 127)) << 23);
                    L0 = (active ? e03 : L0) * scR;
                    L1 = (active ? e13 : L1) * scR;
                    L2 = (active ? e23 : L2) * scR;
                    L3 = (active ? e33 : L3) * scR;
                    carry = U3 * scR;
                    M = M - dm;
                }
            }
            __syncthreads();
        }

        if (is31 && isLast)
            out[0] = ((float)outM - lg2f(outE)) * LN2;
    }
}

// ---------------- host orchestration ----------------
extern "C" void kernel_launch(void* const* d_in, const int* in_sizes, int n_in,
                              void* d_out, int out_size) {
    const float* x    = (const float*)d_in[0];
    const float* y    = (const float*)d_in[1];
    const float* Wih1 = (const float*)d_in[2];
    const float* Whh1 = (const float*)d_in[3];
    const float* bih1 = (const float*)d_in[4];
    const float* bhh1 = (const float*)d_in[5];
    const float* Wih2 = (const float*)d_in[6];
    const float* Whh2 = (const float*)d_in[7];
    const float* bih2 = (const float*)d_in[8];
    const float* bhh2 = (const float*)d_in[9];
    const float* W1   = (const float*)d_in[10];
    const float* b1   = (const float*)d_in[11];
    float* out = (float*)d_out;

    float *seq, *gi, *h1all, *whT1, *whT2;
    cudaGetSymbolAddress((void**)&seq,   g_seq);
    cudaGetSymbolAddress((void**)&gi,    g_gi);
    cudaGetSymbolAddress((void**)&h1all, g_h1all);
    cudaGetSymbolAddress((void**)&whT1,  g_WhhT1);
    cudaGetSymbolAddress((void**)&whT2,  g_WhhT2);

    const int GRU_SMEM = (32 * HID + 32 * G3) * 4;   // 64 KB
    cudaFuncSetAttribute(gru_layer_kernel,
                         cudaFuncAttributeMaxDynamicSharedMemorySize, GRU_SMEM);
    const int DTW_SMEM = 65536 + 1024;               // 64KB Dbuf + in/out boxes
    cudaFuncSetAttribute(softdtw_ws4,
                         cudaFuncAttributeMaxDynamicSharedMemorySize, DTW_SMEM);

    // 1) prep
    {
        int total = STEPS * BATCH * IN_F;
        prep_kernel<<<(total + 255) / 256, 256>>>(x, y, Whh1, Whh2);
    }

    // 2) layer-1 input gates: seq @ Wih1^T  (K=72)
    sgemm_db<8><<<dim3(G3 / 128, (STEPS * BATCH) / 128), 256>>>(
        seq, Wih1, bih1, gi, STEPS * BATCH, G3, IN_F);

    // 3) layer-1 recurrence
    gru_layer_kernel<<<BATCH / 32, 512, GRU_SMEM>>>(
        gi, (const float4*)whT1, bhh1, h1all, nullptr, nullptr);

    // 4) layer-2 input gates: h1all @ Wih2^T  (K=128)
    sgemm_db<16><<<dim3(G3 / 128, (STEPS * BATCH) / 128), 256>>>(
        h1all, Wih2, bih2, gi, STEPS * BATCH, G3, HID);

    // 5) layer-2 recurrence + fused feature projection
    gru_layer_kernel<<<BATCH / 32, 512, GRU_SMEM>>>(
        gi, (const float4*)whT2, bhh2, nullptr, W1, b1);

    // 6) pairwise distances -> probability domain, staged layout
    pairdist_kernel<<<dim3(NW / 32, NW / 32), dim3(32, 32)>>>();

    // 7) soft-DTW warp-specialized wavefront, 4-deep smem-staged D
    softdtw_ws4<<<NSTRIP4, 64, DTW_SMEM>>>(out);
}

// round 15
// speedup vs baseline: 1.5861x; 1.0142x over previous
#include <cuda_runtime.h>
#include <math.h>

#define T_LEN   8196
#define WIN     8
#define STRIDE  4
#define NW      2048
#define BATCH   4096
#define IN_F    72
#define HID     128
#define G3      384
#define FEAT    30
#define STEPS   8
#define LOG2E   1.44269504f
#define LN2     0.693147180559945f

#define NSTRIP4 16
#define QCOLS   512
#define SS4_CHUNKS 68
#define T4PAD   548

// ---------------- static scratch ----------------
__device__ float g_seq  [STEPS * BATCH * IN_F];
__device__ float g_gi   [STEPS * BATCH * G3];
__device__ float g_h1all[STEPS * BATCH * HID];
__device__ float g_feat [BATCH * FEAT];
__device__ float g_Ds4  [NSTRIP4 * T4PAD * 32 * 16];  // [s][t][ri][lane] float4(rj), p = 2^(-d*lg2e)
__device__ float g_WhhT1[HID * G3];
__device__ float g_WhhT2[HID * G3];
__device__ float4 g_row8[NSTRIP4 * 1024];
__device__ int   g_flag2[NSTRIP4 * 32];

// ---------------- PTX helpers ----------------
__device__ __forceinline__ float ex2f(float x) {
    float r; asm("ex2.approx.ftz.f32 %0, %1;" : "=f"(r) : "f"(x)); return r;
}
__device__ __forceinline__ float lg2f(float x) {
    float r; asm("lg2.approx.ftz.f32 %0, %1;" : "=f"(r) : "f"(x)); return r;
}
__device__ __forceinline__ int ldacq(const int* p) {
    int v; asm volatile("ld.acquire.gpu.global.b32 %0, [%1];" : "=r"(v) : "l"(p) : "memory"); return v;
}
__device__ __forceinline__ void sts4_pred(unsigned addr, float a, float b, float c, float d, int pred) {
    asm volatile("{\n\t.reg .pred p;\n\tsetp.ne.s32 p, %0, 0;\n\t@p st.shared.v4.f32 [%1], {%2, %3, %4, %5};\n\t}"
                 :: "r"(pred), "r"(addr), "f"(a), "f"(b), "f"(c), "f"(d) : "memory");
}
__device__ __forceinline__ void cpasync16(unsigned saddr, const void* gaddr) {
    asm volatile("cp.async.cg.shared.global [%0], [%1], 16;" :: "r"(saddr), "l"(gaddr));
}

// ---------------- prep ----------------
__global__ void prep_kernel(const float* __restrict__ x, const float* __restrict__ y,
                            const float* __restrict__ Whh1, const float* __restrict__ Whh2) {
    int idx = blockIdx.x * blockDim.x + threadIdx.x;
    const int total = STEPS * BATCH * IN_F;
    if (idx < total) {
        int f = idx % IN_F;
        int b = (idx / IN_F) % BATCH;
        int s = idx / (IN_F * BATCH);
        const float* src = (b < NW) ? x : y;
        int w = b & (NW - 1);
        g_seq[idx] = src[(size_t)f * T_LEN + w * STRIDE + s];
    }
    if (idx < HID * G3) {
        int k = idx / G3, n = idx % G3;
        g_WhhT1[idx] = Whh1[(size_t)n * HID + k];
        g_WhhT2[idx] = Whh2[(size_t)n * HID + k];
    }
    if (idx < NSTRIP4) g_flag2[idx * 32] = 0;
}

// ---------------- SGEMM (double-buffered, warp-tiled, 2 CTAs/SM): C = A@B^T + bias ----------------
template<int BK>
__global__ void __launch_bounds__(256, 2)
sgemm_db(const float* __restrict__ A, const float* __restrict__ Bw,
         const float* __restrict__ bias, float* __restrict__ C,
         int M, int N, int K) {
    constexpr int BM = 128, BN = 128;
    constexpr int PAD = 4;
    constexpr int C4S = BK / 4;
    constexpr int NL  = (BM * BK / 4) / 256;

    __shared__ float As[2][BK][BM + PAD];
    __shared__ float Bs[2][BK][BN + PAD];

    const int tid = threadIdx.x;
    const int rb = blockIdx.y * BM;
    const int cb = blockIdx.x * BN;
    const int warp = tid >> 5, lane = tid & 31;
    const int wr = (warp & 3) * 32;
    const int wc = (warp >> 2) * 64;
    const int lr = ((lane >> 3) & 3) * 8;
    const int lc = (lane & 7) * 8;

    const int nt = K / BK;

    float4 aR[NL], bR[NL];
    int lrow[NL], lcc[NL];
#pragma unroll
    for (int i = 0; i < NL; ++i) {
        int idx = tid + i * 256;
        lrow[i] = idx / C4S;
        lcc[i]  = idx % C4S;
    }

    auto loadT = [&](int t) {
#pragma unroll
        for (int i = 0; i < NL; ++i) {
            aR[i] = *(const float4*)&A[(size_t)(rb + lrow[i]) * K + t * BK + lcc[i] * 4];
            bR[i] = *(const float4*)&Bw[(size_t)(cb + lrow[i]) * K + t * BK + lcc[i] * 4];
        }
    };
    auto storeT = [&](int buf) {
#pragma unroll
        for (int i = 0; i < NL; ++i) {
            As[buf][lcc[i] * 4 + 0][lrow[i]] = aR[i].x;
            As[buf][lcc[i] * 4 + 1][lrow[i]] = aR[i].y;
            As[buf][lcc[i] * 4 + 2][lrow[i]] = aR[i].z;
            As[buf][lcc[i] * 4 + 3][lrow[i]] = aR[i].w;
            Bs[buf][lcc[i] * 4 + 0][lrow[i]] = bR[i].x;
            Bs[buf][lcc[i] * 4 + 1][lrow[i]] = bR[i].y;
            Bs[buf][lcc[i] * 4 + 2][lrow[i]] = bR[i].z;
            Bs[buf][lcc[i] * 4 + 3][lrow[i]] = bR[i].w;
        }
    };

    float acc[8][8];
#pragma unroll
    for (int i = 0; i < 8; i++)
#pragma unroll
        for (int j = 0; j < 8; j++) acc[i][j] = 0.f;

    loadT(0);
    storeT(0);
    __syncthreads();

    for (int t = 0; t < nt; ++t) {
        const int cur = t & 1;
        if (t + 1 < nt) loadT(t + 1);
#pragma unroll
        for (int kk = 0; kk < BK; ++kk) {
            float4 a0 = *(const float4*)&As[cur][kk][wr + lr];
            float4 a1 = *(const float4*)&As[cur][kk][wr + lr + 4];
            float4 b0 = *(const float4*)&Bs[cur][kk][wc + lc];
            float4 b1 = *(const float4*)&Bs[cur][kk][wc + lc + 4];
            float ra[8]  = {a0.x, a0.y, a0.z, a0.w, a1.x, a1.y, a1.z, a1.w};
            float rbv[8] = {b0.x, b0.y, b0.z, b0.w, b1.x, b1.y, b1.z, b1.w};
#pragma unroll
            for (int i = 0; i < 8; i++)
#pragma unroll
                for (int j = 0; j < 8; j++)
                    acc[i][j] += ra[i] * rbv[j];
        }
        if (t + 1 < nt) storeT((t + 1) & 1);
        __syncthreads();
    }

    float bv[8];
#pragma unroll
    for (int j = 0; j < 8; j++) bv[j] = bias[cb + wc + lc + j];
#pragma unroll
    for (int i = 0; i < 8; i++) {
        int row = rb + wr + lr + i;
        float4 o0 = make_float4(acc[i][0] + bv[0], acc[i][1] + bv[1],
                                acc[i][2] + bv[2], acc[i][3] + bv[3]);
        float4 o1 = make_float4(acc[i][4] + bv[4], acc[i][5] + bv[5],
                                acc[i][6] + bv[6], acc[i][7] + bv[7]);
        *(float4*)&C[(size_t)row * N + cb + wc + lc]     = o0;
        *(float4*)&C[(size_t)row * N + cb + wc + lc + 4] = o1;
    }
}

// ---------------- persistent GRU layer (split-K; vectorized hsm loads) ----------------
__global__ void __launch_bounds__(512)
gru_layer_kernel(const float* __restrict__ gi,
                 const float4* __restrict__ W4,
                 const float* __restrict__ bhh,
                 float* __restrict__ hall,
                 const float* __restrict__ W1,
                 const float* __restrict__ b1)
{
    extern __shared__ float sraw[];
    float (*hsm)[HID] = (float (*)[HID])sraw;
    float (*psum)[G3] = (float (*)[G3])(sraw + 32 * HID);

    const int tid = threadIdx.x;
    const int kh  = tid >> 8;
    const int gt  = tid & 255;
    const int tr  = gt >> 5;
    const int tc  = gt & 31;
    const int rb  = blockIdx.x * 32;
    const int kbase = kh * 64;
    const bool comb = (kh == 0) ? (tr < 4) : (tr >= 4);

    for (int m = tid; m < 32 * HID; m += 512) sraw[m] = 0.f;
    __syncthreads();

    float bq[3][4];
#pragma unroll
    for (int g = 0; g < 3; ++g) {
        float4 bb = *(const float4*)&bhh[g * HID + tc * 4];
        bq[g][0] = bb.x; bq[g][1] = bb.y; bq[g][2] = bb.z; bq[g][3] = bb.w;
    }

    for (int step = 0; step < STEPS; ++step) {
        float acc[4][3][4];
#pragma unroll
        for (int ii = 0; ii < 4; ++ii)
#pragma unroll
            for (int g = 0; g < 3; ++g)
#pragma unroll
                for (int o = 0; o < 4; ++o) acc[ii][g][o] = 0.f;

#pragma unroll 2
        for (int kk4 = 0; kk4 < 64; kk4 += 4) {
            const int k0 = kbase + kk4;
            float a_[4][4];
#pragma unroll
            for (int ii = 0; ii < 4; ++ii) {
                float4 a4 = *(const float4*)&hsm[tr * 4 + ii][k0];
                a_[ii][0] = a4.x; a_[ii][1] = a4.y; a_[ii][2] = a4.z; a_[ii][3] = a4.w;
            }
#pragma unroll
            for (int j = 0; j < 4; ++j) {
#pragma unroll
                for (int g = 0; g < 3; ++g) {
                    float4 b = __ldg(&W4[(k0 + j) * 96 + g * 32 + tc]);
#pragma unroll
                    for (int ii = 0; ii < 4; ++ii) {
                        acc[ii][g][0] += a_[ii][j] * b.x;
                        acc[ii][g][1] += a_[ii][j] * b.y;
                        acc[ii][g][2] += a_[ii][j] * b.z;
                        acc[ii][g][3] += a_[ii][j] * b.w;
                    }
                }
            }
        }

        if (!comb) {
#pragma unroll
            for (int ii = 0; ii < 4; ++ii) {
                const int r = tr * 4 + ii;
#pragma unroll
                for (int g = 0; g < 3; ++g)
                    *(float4*)&psum[r][g * HID + tc * 4] =
                        make_float4(acc[ii][g][0], acc[ii][g][1],
                                    acc[ii][g][2], acc[ii][g][3]);
            }
        }
        __syncthreads();

        if (comb) {
            const size_t rowbase = (size_t)step * BATCH + rb;
#pragma unroll
            for (int ii = 0; ii < 4; ++ii) {
                const int r = tr * 4 + ii;
                const float* gb = gi + (rowbase + r) * G3;
                float4 gr = __ldg((const float4*)(gb + tc * 4));
                float4 gz = __ldg((const float4*)(gb + HID + tc * 4));
                float4 gn = __ldg((const float4*)(gb + 2 * HID + tc * 4));
                float4 p0 = *(const float4*)&psum[r][0 * HID + tc * 4];
                float4 p1 = *(const float4*)&psum[r][1 * HID + tc * 4];
                float4 p2 = *(const float4*)&psum[r][2 * HID + tc * 4];
                float4 ho = *(const float4*)&hsm[r][tc * 4];
                float irv[4] = {gr.x, gr.y, gr.z, gr.w};
                float izv[4] = {gz.x, gz.y, gz.z, gz.w};
                float inv[4] = {gn.x, gn.y, gn.z, gn.w};
                float hv [4] = {ho.x, ho.y, ho.z, ho.w};
                float pr [4] = {p0.x, p0.y, p0.z, p0.w};
                float pz [4] = {p1.x, p1.y, p1.z, p1.w};
                float pn [4] = {p2.x, p2.y, p2.z, p2.w};
                float ov[4];
#pragma unroll
                for (int o = 0; o < 4; ++o) {
                    float hr = acc[ii][0][o] + pr[o] + bq[0][o];
                    float hz = acc[ii][1][o] + pz[o] + bq[1][o];
                    float hn = acc[ii][2][o] + pn[o] + bq[2][o];
                    float rg = 1.f / (1.f + __expf(-(irv[o] + hr)));
                    float zg = 1.f / (1.f + __expf(-(izv[o] + hz)));
                    float ng = tanhf(inv[o] + rg * hn);
                    ov[o] = (1.f - zg) * ng + zg * hv[o];
                }
                float4 hn4 = make_float4(ov[0], ov[1], ov[2], ov[3]);
                *(float4*)&hsm[r][tc * 4] = hn4;
                if (hall)
                    *(float4*)&hall[(rowbase + r) * HID + tc * 4] = hn4;
            }
        }
        __syncthreads();
    }

    if (W1) {
        for (int t = tid; t < 32 * FEAT; t += 512) {
            int r = t / FEAT, o = t % FEAT;
            float s = b1[o];
            const float* w = W1 + (size_t)o * HID;
#pragma unroll 8
            for (int k = 0; k < HID; ++k) s += hsm[r][k] * w[k];
            g_feat[(size_t)(rb + r) * FEAT + o] = s;
        }
    }
}

// ---------------- pairwise: p = 2^(-d*lg2e), layout [s][t][ri][lane] float4(rj) ----------------
__global__ void pairdist_kernel() {
    __shared__ float s1[32][31];
    __shared__ float s2[32][31];
    __shared__ float dtile[32][33];
    int tid = threadIdx.y * 32 + threadIdx.x;
    int i0 = blockIdx.y * 32, j0 = blockIdx.x * 32;
    for (int idx = tid; idx < 32 * FEAT; idx += 1024) {
        int r = idx / FEAT, c = idx % FEAT;
        s1[r][c] = g_feat[(size_t)(i0 + r) * FEAT + c];
        s2[r][c] = g_feat[(size_t)(NW + j0 + r) * FEAT + c];
    }
    __syncthreads();
    {
        float d = 0.f;
#pragma unroll
        for (int c = 0; c < FEAT; c++) {
            float t = s1[threadIdx.y][c] - s2[threadIdx.x][c];
            d += t * t;
        }
        dtile[threadIdx.y][threadIdx.x] = ex2f(fmaxf(-d * LOG2E, -100.f));
    }
    __syncthreads();
    if (tid < 256) {
        int ri  = tid & 3;
        int cq8 = (tid >> 2) & 7;
        int lq  = (tid >> 5) & 7;
        int row = lq * 4 + ri;
        float4 v = make_float4(dtile[row][cq8 * 4 + 0], dtile[row][cq8 * 4 + 1],
                               dtile[row][cq8 * 4 + 2], dtile[row][cq8 * 4 + 3]);
        int i = i0 + row;
        int s = i >> 7;
        int l = (i >> 2) & 31;
        int cq = (j0 >> 2) + cq8;
        int t = cq + l;
        *(float4*)&g_Ds4[((((size_t)s * T4PAD + t) * 4 + ri) * 32 + l) * 4] = v;
    }
}

// ---------------- soft-DTW: 4x4 blocks/lane, warp-specialized, 4-deep D staging ----------------
__global__ void __launch_bounds__(64)
softdtw_ws4(float* __restrict__ out) {
    extern __shared__ char sdtw[];
    float4* Dbufp = (float4*)sdtw;
    float4 (*inbox)[16]  = (float4 (*)[16])(sdtw + 65536);
    float4 (*outbox)[16] = (float4 (*)[16])(sdtw + 65536 + 512);

    const int s = blockIdx.x;
    const int tid = threadIdx.x;
    const int warpi = tid >> 5;
    const int lane = tid & 31;

    if (tid < 32) inbox[tid >> 4][tid & 15] = make_float4(0.f, 0.f, 0.f, 0.f);
    __syncthreads();

    if (warpi == 1) {
        const float4* rowprev8 = g_row8 + (size_t)(s - 1) * 1024;
        float4* rowmine8 = g_row8 + (size_t)s * 1024;
        int* myflag = &g_flag2[s * 32];
        const int* prevflag = &g_flag2[(s - 1) * 32];
        const int doIn  = (s > 0);
        const int doOut = (s < NSTRIP4 - 1);

        const float4* dsrc = ((const float4*)g_Ds4) + (size_t)s * T4PAD * 128;
        unsigned dbase = (unsigned)__cvta_generic_to_shared(Dbufp);

        auto stageD = [&](int CC) {
            const float4* g = dsrc + (size_t)CC * 1024;
            unsigned sb = dbase + (unsigned)((CC & 3) * 16384);
#pragma unroll
            for (int k = 0; k < 32; ++k) {
                int u = k * 32 + lane;
                cpasync16(sb + (unsigned)(u * 16), g + u);
            }
            asm volatile("cp.async.commit_group;" ::: "memory");
        };

        stageD(0); stageD(1); stageD(2);
        if (doIn && lane < 16) {
            while (ldacq(prevflag) < 1) { }
            inbox[0][lane] = __ldg(&rowprev8[lane]);
        }
        asm volatile("cp.async.wait_group 2;" ::: "memory");
        __syncthreads();

        for (int I = 0; I <= SS4_CHUNKS; ++I) {
            if (lane >= 16) {
                const int Cp = I - 1;
                if (doOut && Cp >= 0) {
                    int kk = lane - 16;
                    int q = kk >> 1, h = kk & 1;
                    int cq = Cp * 8 - 31 + q;
                    if (cq >= 0 && cq < QCOLS)
                        rowmine8[cq * 2 + h] = outbox[Cp & 1][kk];
                }
            }
            __syncwarp();
            if (lane == 16 && doOut && I >= 5) {
                __threadfence();
                asm volatile("red.relaxed.gpu.global.add.u32 [%0], 1;"
                             :: "l"(myflag) : "memory");
            }
            if (I + 3 < SS4_CHUNKS) stageD(I + 3);
            if (lane < 16) {
                const int Cn = I + 1;
                if (doIn && Cn < 64) {
                    while (ldacq(prevflag) < Cn + 1) { }
                    inbox[Cn & 1][lane] = __ldg(&rowprev8[Cn * 16 + lane]);
                }
            }
            asm volatile("cp.async.wait_group 2;" ::: "memory");
            __syncthreads();
        }
    } else {
        const int is31 = (lane == 31);
        const int isLast = (s == NSTRIP4 - 1);
        const int pubp = is31 & !isLast;

        float L0 = 0.f, L1 = 0.f, L2 = 0.f, L3 = 0.f;
        float carry = 0.f;
        float sh0 = 0.f, sh1 = 0.f, sh2 = 0.f, sh3 = 0.f;
        int   M = 0, shM = 0;
        if (s == 0 && lane == 0) carry = 1.f;

        unsigned obase = (unsigned)__cvta_generic_to_shared(&outbox[0][0]);

        float outE = 1.f; int outM = 0;

        __syncthreads();

        for (int I = 0; I <= SS4_CHUNKS; ++I) {
            if (I < SS4_CHUNKS) {
#pragma unroll
                for (int q = 0; q < 8; ++q) {
                    const int c = I * 8 + q - lane;

                    const float4* Dq = Dbufp + (I & 3) * 1024 + q * 128 + lane;
                    float4 p0 = Dq[0];
                    float4 p1 = Dq[32];
                    float4 p2 = Dq[64];
                    float4 p3 = Dq[96];

                    float4 rE = inbox[I & 1][2 * q];
                    float  rM = inbox[I & 1][2 * q + 1].x;
                    if (I == 0 && q == 0 && s > 0 && lane == 0) M = (int)rM;

                    float nB0 = __shfl_up_sync(0xffffffffu, sh0, 1);
                    float nB1 = __shfl_up_sync(0xffffffffu, sh1, 1);
                    float nB2 = __shfl_up_sync(0xffffffffu, sh2, 1);
                    float nB3 = __shfl_up_sync(0xffffffffu, sh3, 1);
                    int   nM  = __shfl_up_sync(0xffffffffu, shM, 1);
                    if (lane == 0) { nB0 = rE.x; nB1 = rE.y; nB2 = rE.z; nB3 = rE.w; nM = (int)rM; }
                    if (c < 0) M = nM;
                    int dmm = M - nM;
                    dmm = dmm < -126 ? -126 : (dmm > 126 ? 126 : dmm);
                    float sc = __uint_as_float((unsigned)(dmm + 127) << 23);
                    float U0 = nB0 * sc, U1 = nB1 * sc, U2 = nB2 * sc, U3 = nB3 * sc;

                    float e00 = p0.x * ((carry + U0) + L0);
                    float e01 = p0.y * ((U0 + U1) + e00);
                    float e02 = p0.z * ((U1 + U2) + e01);
                    float e03 = p0.w * ((U2 + U3) + e02);
                    float e10 = p1.x * ((L0 + e00) + L1);
                    float e11 = p1.y * ((e00 + e01) + e10);
                    float e12 = p1.z * ((e01 + e02) + e11);
                    float e13 = p1.w * ((e02 + e03) + e12);
                    float e20 = p2.x * ((L1 + e10) + L2);
                    float e21 = p2.y * ((e10 + e11) + e20);
                    float e22 = p2.z * ((e11 + e12) + e21);
                    float e23 = p2.w * ((e12 + e13) + e22);
                    float e30 = p3.x * ((L2 + e20) + L3);
                    float e31 = p3.y * ((e20 + e21) + e30);
                    float e32 = p3.z * ((e21 + e22) + e31);
                    float e33 = p3.w * ((e22 + e23) + e32);

                    const int active = (c >= 0) & (c < QCOLS);

                    sts4_pred(obase + (unsigned)(((I & 1) * 16 + 2 * q) * 16),
                              e30, e31, e32, e33, pubp);
                    sts4_pred(obase + (unsigned)(((I & 1) * 16 + 2 * q + 1) * 16),
                              (float)M, 0.f, 0.f, 0.f, pubp);

                    outE = (is31 & isLast & active & (c == QCOLS - 1)) ? e33 : outE;
                    outM = (is31 & isLast & active & (c == QCOLS - 1)) ? M   : outM;

                    sh0 = active ? e30 : sh0;
                    sh1 = active ? e31 : sh1;
                    sh2 = active ? e32 : sh2;
                    sh3 = active ? e33 : sh3;
                    shM = active ? M   : shM;

                    int eb = (__float_as_int(e33) >> 23) & 255;
                    int doR = active & (eb > 0) & (eb < 254);
                    int dm = doR ? (eb - 127) : 0;
                    float scR = __uint_as_float((unsigned)(254 - (doR ? eb : 127)) << 23);
                    L0 = (active ? e03 : L0) * scR;
                    L1 = (active ? e13 : L1) * scR;
                    L2 = (active ? e23 : L2) * scR;
                    L3 = (active ? e33 : L3) * scR;
                    carry = U3 * scR;
                    M = M - dm;
                }
            }
            __syncthreads();
        }

        if (is31 && isLast)
            out[0] = ((float)outM - lg2f(outE)) * LN2;
    }
}

// ---------------- host orchestration ----------------
extern "C" void kernel_launch(void* const* d_in, const int* in_sizes, int n_in,
                              void* d_out, int out_size) {
    const float* x    = (const float*)d_in[0];
    const float* y    = (const float*)d_in[1];
    const float* Wih1 = (const float*)d_in[2];
    const float* Whh1 = (const float*)d_in[3];
    const float* bih1 = (const float*)d_in[4];
    const float* bhh1 = (const float*)d_in[5];
    const float* Wih2 = (const float*)d_in[6];
    const float* Whh2 = (const float*)d_in[7];
    const float* bih2 = (const float*)d_in[8];
    const float* bhh2 = (const float*)d_in[9];
    const float* W1   = (const float*)d_in[10];
    const float* b1   = (const float*)d_in[11];
    float* out = (float*)d_out;

    float *seq, *gi, *h1all, *whT1, *whT2;
    cudaGetSymbolAddress((void**)&seq,   g_seq);
    cudaGetSymbolAddress((void**)&gi,    g_gi);
    cudaGetSymbolAddress((void**)&h1all, g_h1all);
    cudaGetSymbolAddress((void**)&whT1,  g_WhhT1);
    cudaGetSymbolAddress((void**)&whT2,  g_WhhT2);

    const int GRU_SMEM = (32 * HID + 32 * G3) * 4;   // 64 KB
    cudaFuncSetAttribute(gru_layer_kernel,
                         cudaFuncAttributeMaxDynamicSharedMemorySize, GRU_SMEM);
    const int DTW_SMEM = 65536 + 1024;
    cudaFuncSetAttribute(softdtw_ws4,
                         cudaFuncAttributeMaxDynamicSharedMemorySize, DTW_SMEM);

    // 1) prep
    {
        int total = STEPS * BATCH * IN_F;
        prep_kernel<<<(total + 255) / 256, 256>>>(x, y, Whh1, Whh2);
    }

    // 2) layer-1 input gates: seq @ Wih1^T  (K=72, BK=8 -> 2 CTAs/SM)
    sgemm_db<8><<<dim3(G3 / 128, (STEPS * BATCH) / 128), 256>>>(
        seq, Wih1, bih1, gi, STEPS * BATCH, G3, IN_F);

    // 3) layer-1 recurrence
    gru_layer_kernel<<<BATCH / 32, 512, GRU_SMEM>>>(
        gi, (const float4*)whT1, bhh1, h1all, nullptr, nullptr);

    // 4) layer-2 input gates: h1all @ Wih2^T  (K=128, BK=8 -> 2 CTAs/SM)
    sgemm_db<8><<<dim3(G3 / 128, (STEPS * BATCH) / 128), 256>>>(
        h1all, Wih2, bih2, gi, STEPS * BATCH, G3, HID);

    // 5) layer-2 recurrence + fused feature projection
    gru_layer_kernel<<<BATCH / 32, 512, GRU_SMEM>>>(
        gi, (const float4*)whT2, bhh2, nullptr, W1, b1);

    // 6) pairwise distances
    pairdist_kernel<<<dim3(NW / 32, NW / 32), dim3(32, 32)>>>();

    // 7) soft-DTW
    softdtw_ws4<<<NSTRIP4, 64, DTW_SMEM>>>(out);
}

// round 16
// speedup vs baseline: 1.5990x; 1.0082x over previous
#include <cuda_runtime.h>
#include <math.h>

#define T_LEN   8196
#define WIN     8
#define STRIDE  4
#define NW      2048
#define BATCH   4096
#define IN_F    72
#define HID     128
#define G3      384
#define FEAT    30
#define STEPS   8
#define LOG2E   1.44269504f
#define LN2     0.693147180559945f

#define NSTRIP4 16
#define QCOLS   512
#define SS4_CHUNKS 68
#define T4PAD   548

// ---------------- static scratch ----------------
__device__ float g_seq  [STEPS * BATCH * IN_F];
__device__ float g_gi   [STEPS * BATCH * G3];
__device__ float g_h1all[STEPS * BATCH * HID];
__device__ float g_feat [BATCH * FEAT];
__device__ float g_Ds4  [NSTRIP4 * T4PAD * 32 * 16];
__device__ float g_WhhT1[HID * G3];
__device__ float g_WhhT2[HID * G3];
__device__ float4 g_row8[NSTRIP4 * 1024];
__device__ int   g_flag2[NSTRIP4 * 32];

// ---------------- PTX helpers ----------------
__device__ __forceinline__ float ex2f(float x) {
    float r; asm("ex2.approx.ftz.f32 %0, %1;" : "=f"(r) : "f"(x)); return r;
}
__device__ __forceinline__ float lg2f(float x) {
    float r; asm("lg2.approx.ftz.f32 %0, %1;" : "=f"(r) : "f"(x)); return r;
}
__device__ __forceinline__ int ldacq(const int* p) {
    int v; asm volatile("ld.acquire.gpu.global.b32 %0, [%1];" : "=r"(v) : "l"(p) : "memory"); return v;
}
__device__ __forceinline__ void sts4_pred(unsigned addr, float a, float b, float c, float d, int pred) {
    asm volatile("{\n\t.reg .pred p;\n\tsetp.ne.s32 p, %0, 0;\n\t@p st.shared.v4.f32 [%1], {%2, %3, %4, %5};\n\t}"
                 :: "r"(pred), "r"(addr), "f"(a), "f"(b), "f"(c), "f"(d) : "memory");
}
__device__ __forceinline__ void cpasync16(unsigned saddr, const void* gaddr) {
    asm volatile("cp.async.cg.shared.global [%0], [%1], 16;" :: "r"(saddr), "l"(gaddr));
}

// ---------------- prep ----------------
__global__ void prep_kernel(const float* __restrict__ x, const float* __restrict__ y,
                            const float* __restrict__ Whh1, const float* __restrict__ Whh2) {
    int idx = blockIdx.x * blockDim.x + threadIdx.x;
    const int total = STEPS * BATCH * IN_F;
    if (idx < total) {
        int f = idx % IN_F;
        int b = (idx / IN_F) % BATCH;
        int s = idx / (IN_F * BATCH);
        const float* src = (b < NW) ? x : y;
        int w = b & (NW - 1);
        g_seq[idx] = src[(size_t)f * T_LEN + w * STRIDE + s];
    }
    if (idx < HID * G3) {
        int k = idx / G3, n = idx % G3;
        g_WhhT1[idx] = Whh1[(size_t)n * HID + k];
        g_WhhT2[idx] = Whh2[(size_t)n * HID + k];
    }
    if (idx < NSTRIP4) g_flag2[idx * 32] = 0;
}

// ---------------- SGEMM (double-buffered, warp-tiled, 2 CTAs/SM): C = A@B^T + bias ----------------
template<int BK>
__global__ void __launch_bounds__(256, 2)
sgemm_db(const float* __restrict__ A, const float* __restrict__ Bw,
         const float* __restrict__ bias, float* __restrict__ C,
         int M, int N, int K) {
    constexpr int BM = 128, BN = 128;
    constexpr int PAD = 4;
    constexpr int C4S = BK / 4;
    constexpr int NL  = (BM * BK / 4) / 256;

    __shared__ float As[2][BK][BM + PAD];
    __shared__ float Bs[2][BK][BN + PAD];

    const int tid = threadIdx.x;
    const int rb = blockIdx.y * BM;
    const int cb = blockIdx.x * BN;
    const int warp = tid >> 5, lane = tid & 31;
    const int wr = (warp & 3) * 32;
    const int wc = (warp >> 2) * 64;
    const int lr = ((lane >> 3) & 3) * 8;
    const int lc = (lane & 7) * 8;

    const int nt = K / BK;

    float4 aR[NL], bR[NL];
    int lrow[NL], lcc[NL];
#pragma unroll
    for (int i = 0; i < NL; ++i) {
        int idx = tid + i * 256;
        lrow[i] = idx / C4S;
        lcc[i]  = idx % C4S;
    }

    auto loadT = [&](int t) {
#pragma unroll
        for (int i = 0; i < NL; ++i) {
            aR[i] = *(const float4*)&A[(size_t)(rb + lrow[i]) * K + t * BK + lcc[i] * 4];
            bR[i] = *(const float4*)&Bw[(size_t)(cb + lrow[i]) * K + t * BK + lcc[i] * 4];
        }
    };
    auto storeT = [&](int buf) {
#pragma unroll
        for (int i = 0; i < NL; ++i) {
            As[buf][lcc[i] * 4 + 0][lrow[i]] = aR[i].x;
            As[buf][lcc[i] * 4 + 1][lrow[i]] = aR[i].y;
            As[buf][lcc[i] * 4 + 2][lrow[i]] = aR[i].z;
            As[buf][lcc[i] * 4 + 3][lrow[i]] = aR[i].w;
            Bs[buf][lcc[i] * 4 + 0][lrow[i]] = bR[i].x;
            Bs[buf][lcc[i] * 4 + 1][lrow[i]] = bR[i].y;
            Bs[buf][lcc[i] * 4 + 2][lrow[i]] = bR[i].z;
            Bs[buf][lcc[i] * 4 + 3][lrow[i]] = bR[i].w;
        }
    };

    float acc[8][8];
#pragma unroll
    for (int i = 0; i < 8; i++)
#pragma unroll
        for (int j = 0; j < 8; j++) acc[i][j] = 0.f;

    loadT(0);
    storeT(0);
    __syncthreads();

    for (int t = 0; t < nt; ++t) {
        const int cur = t & 1;
        if (t + 1 < nt) loadT(t + 1);
#pragma unroll
        for (int kk = 0; kk < BK; ++kk) {
            float4 a0 = *(const float4*)&As[cur][kk][wr + lr];
            float4 a1 = *(const float4*)&As[cur][kk][wr + lr + 4];
            float4 b0 = *(const float4*)&Bs[cur][kk][wc + lc];
            float4 b1 = *(const float4*)&Bs[cur][kk][wc + lc + 4];
            float ra[8]  = {a0.x, a0.y, a0.z, a0.w, a1.x, a1.y, a1.z, a1.w};
            float rbv[8] = {b0.x, b0.y, b0.z, b0.w, b1.x, b1.y, b1.z, b1.w};
#pragma unroll
            for (int i = 0; i < 8; i++)
#pragma unroll
                for (int j = 0; j < 8; j++)
                    acc[i][j] += ra[i] * rbv[j];
        }
        if (t + 1 < nt) storeT((t + 1) & 1);
        __syncthreads();
    }

    float bv[8];
#pragma unroll
    for (int j = 0; j < 8; j++) bv[j] = bias[cb + wc + lc + j];
#pragma unroll
    for (int i = 0; i < 8; i++) {
        int row = rb + wr + lr + i;
        float4 o0 = make_float4(acc[i][0] + bv[0], acc[i][1] + bv[1],
                                acc[i][2] + bv[2], acc[i][3] + bv[3]);
        float4 o1 = make_float4(acc[i][4] + bv[4], acc[i][5] + bv[5],
                                acc[i][6] + bv[6], acc[i][7] + bv[7]);
        *(float4*)&C[(size_t)row * N + cb + wc + lc]     = o0;
        *(float4*)&C[(size_t)row * N + cb + wc + lc + 4] = o1;
    }
}

// ---------------- GRU layer: warp-autonomous (no block barriers in the step loop) ----------------
// 256 CTAs x 256 threads; CTA owns 16 batch rows; warp tr owns rows {2tr, 2tr+1}.
// Thread (tr,tc): 2 rows x 4 cols x 3 gates -> acc 24 regs; full K per thread.
__global__ void __launch_bounds__(256, 2)
gru_layer_kernel(const float* __restrict__ gi,
                 const float4* __restrict__ W4,    // [HID][G3] as float4
                 const float* __restrict__ bhh,
                 float* __restrict__ hall,
                 const float* __restrict__ W1,
                 const float* __restrict__ b1)
{
    __shared__ float hsm[16][HID];     // 8 KB

    const int tid = threadIdx.x;
    const int tr  = tid >> 5;          // warp 0..7 -> rows 2tr, 2tr+1
    const int tc  = tid & 31;
    const int rb  = blockIdx.x * 16;
    const int r0  = tr * 2;

    // each warp zeroes its own 2 rows
    *(float4*)&hsm[r0][tc * 4]     = make_float4(0.f, 0.f, 0.f, 0.f);
    *(float4*)&hsm[r0 + 1][tc * 4] = make_float4(0.f, 0.f, 0.f, 0.f);
    __syncwarp();

    float bq[3][4];
#pragma unroll
    for (int g = 0; g < 3; ++g) {
        float4 bb = *(const float4*)&bhh[g * HID + tc * 4];
        bq[g][0] = bb.x; bq[g][1] = bb.y; bq[g][2] = bb.z; bq[g][3] = bb.w;
    }

    for (int step = 0; step < STEPS; ++step) {
        float acc[2][3][4];
#pragma unroll
        for (int ii = 0; ii < 2; ++ii)
#pragma unroll
            for (int g = 0; g < 3; ++g)
#pragma unroll
                for (int o = 0; o < 4; ++o) acc[ii][g][o] = 0.f;

#pragma unroll 2
        for (int k0 = 0; k0 < HID; k0 += 4) {
            float4 a0 = *(const float4*)&hsm[r0][k0];
            float4 a1 = *(const float4*)&hsm[r0 + 1][k0];
            float av[2][4] = {{a0.x, a0.y, a0.z, a0.w}, {a1.x, a1.y, a1.z, a1.w}};
#pragma unroll
            for (int j = 0; j < 4; ++j) {
#pragma unroll
                for (int g = 0; g < 3; ++g) {
                    float4 b = __ldg(&W4[(k0 + j) * 96 + g * 32 + tc]);
#pragma unroll
                    for (int ii = 0; ii < 2; ++ii) {
                        acc[ii][g][0] += av[ii][j] * b.x;
                        acc[ii][g][1] += av[ii][j] * b.y;
                        acc[ii][g][2] += av[ii][j] * b.z;
                        acc[ii][g][3] += av[ii][j] * b.w;
                    }
                }
            }
        }
        __syncwarp();   // all lanes of this warp done reading rows r0, r0+1

        const size_t rowbase = (size_t)step * BATCH + rb;
#pragma unroll
        for (int ii = 0; ii < 2; ++ii) {
            const int r = r0 + ii;
            const float* gb = gi + (rowbase + r) * G3;
            float4 gr = __ldg((const float4*)(gb + tc * 4));
            float4 gz = __ldg((const float4*)(gb + HID + tc * 4));
            float4 gn = __ldg((const float4*)(gb + 2 * HID + tc * 4));
            float4 ho = *(const float4*)&hsm[r][tc * 4];
            float irv[4] = {gr.x, gr.y, gr.z, gr.w};
            float izv[4] = {gz.x, gz.y, gz.z, gz.w};
            float inv[4] = {gn.x, gn.y, gn.z, gn.w};
            float hv [4] = {ho.x, ho.y, ho.z, ho.w};
            float ov[4];
#pragma unroll
            for (int o = 0; o < 4; ++o) {
                float hr = acc[ii][0][o] + bq[0][o];
                float hz = acc[ii][1][o] + bq[1][o];
                float hn = acc[ii][2][o] + bq[2][o];
                float rg = 1.f / (1.f + __expf(-(irv[o] + hr)));
                float zg = 1.f / (1.f + __expf(-(izv[o] + hz)));
                float ng = tanhf(inv[o] + rg * hn);
                ov[o] = (1.f - zg) * ng + zg * hv[o];
            }
            float4 hn4 = make_float4(ov[0], ov[1], ov[2], ov[3]);
            *(float4*)&hsm[r][tc * 4] = hn4;
            if (hall)
                *(float4*)&hall[(rowbase + r) * HID + tc * 4] = hn4;
        }
        __syncwarp();   // writes visible to warp before next step's reads
    }

    // fused feature projection (block-wide over 16 rows)
    if (W1) {
        __syncthreads();
        for (int t = tid; t < 16 * FEAT; t += 256) {
            int r = t / FEAT, o = t % FEAT;
            float s = b1[o];
            const float* w = W1 + (size_t)o * HID;
#pragma unroll 8
            for (int k = 0; k < HID; ++k) s += hsm[r][k] * w[k];
            g_feat[(size_t)(rb + r) * FEAT + o] = s;
        }
    }
}

// ---------------- pairwise: p = 2^(-d*lg2e), layout [s][t][ri][lane] float4(rj) ----------------
__global__ void pairdist_kernel() {
    __shared__ float s1[32][31];
    __shared__ float s2[32][31];
    __shared__ float dtile[32][33];
    int tid = threadIdx.y * 32 + threadIdx.x;
    int i0 = blockIdx.y * 32, j0 = blockIdx.x * 32;
    for (int idx = tid; idx < 32 * FEAT; idx += 1024) {
        int r = idx / FEAT, c = idx % FEAT;
        s1[r][c] = g_feat[(size_t)(i0 + r) * FEAT + c];
        s2[r][c] = g_feat[(size_t)(NW + j0 + r) * FEAT + c];
    }
    __syncthreads();
    {
        float d = 0.f;
#pragma unroll
        for (int c = 0; c < FEAT; c++) {
            float t = s1[threadIdx.y][c] - s2[threadIdx.x][c];
            d += t * t;
        }
        dtile[threadIdx.y][threadIdx.x] = ex2f(fmaxf(-d * LOG2E, -100.f));
    }
    __syncthreads();
    if (tid < 256) {
        int ri  = tid & 3;
        int cq8 = (tid >> 2) & 7;
        int lq  = (tid >> 5) & 7;
        int row = lq * 4 + ri;
        float4 v = make_float4(dtile[row][cq8 * 4 + 0], dtile[row][cq8 * 4 + 1],
                               dtile[row][cq8 * 4 + 2], dtile[row][cq8 * 4 + 3]);
        int i = i0 + row;
        int s = i >> 7;
        int l = (i >> 2) & 31;
        int cq = (j0 >> 2) + cq8;
        int t = cq + l;
        *(float4*)&g_Ds4[((((size_t)s * T4PAD + t) * 4 + ri) * 32 + l) * 4] = v;
    }
}

// ---------------- soft-DTW: 4x4 blocks/lane, warp-specialized, 4-deep D staging ----------------
__global__ void __launch_bounds__(64)
softdtw_ws4(float* __restrict__ out) {
    extern __shared__ char sdtw[];
    float4* Dbufp = (float4*)sdtw;
    float4 (*inbox)[16]  = (float4 (*)[16])(sdtw + 65536);
    float4 (*outbox)[16] = (float4 (*)[16])(sdtw + 65536 + 512);

    const int s = blockIdx.x;
    const int tid = threadIdx.x;
    const int warpi = tid >> 5;
    const int lane = tid & 31;

    if (tid < 32) inbox[tid >> 4][tid & 15] = make_float4(0.f, 0.f, 0.f, 0.f);
    __syncthreads();

    if (warpi == 1) {
        const float4* rowprev8 = g_row8 + (size_t)(s - 1) * 1024;
        float4* rowmine8 = g_row8 + (size_t)s * 1024;
        int* myflag = &g_flag2[s * 32];
        const int* prevflag = &g_flag2[(s - 1) * 32];
        const int doIn  = (s > 0);
        const int doOut = (s < NSTRIP4 - 1);

        const float4* dsrc = ((const float4*)g_Ds4) + (size_t)s * T4PAD * 128;
        unsigned dbase = (unsigned)__cvta_generic_to_shared(Dbufp);

        auto stageD = [&](int CC) {
            const float4* g = dsrc + (size_t)CC * 1024;
            unsigned sb = dbase + (unsigned)((CC & 3) * 16384);
#pragma unroll
            for (int k = 0; k < 32; ++k) {
                int u = k * 32 + lane;
                cpasync16(sb + (unsigned)(u * 16), g + u);
            }
            asm volatile("cp.async.commit_group;" ::: "memory");
        };

        stageD(0); stageD(1); stageD(2);
        if (doIn && lane < 16) {
            while (ldacq(prevflag) < 1) { }
            inbox[0][lane] = __ldg(&rowprev8[lane]);
        }
        asm volatile("cp.async.wait_group 2;" ::: "memory");
        __syncthreads();

        for (int I = 0; I <= SS4_CHUNKS; ++I) {
            if (lane >= 16) {
                const int Cp = I - 1;
                if (doOut && Cp >= 0) {
                    int kk = lane - 16;
                    int q = kk >> 1, h = kk & 1;
                    int cq = Cp * 8 - 31 + q;
                    if (cq >= 0 && cq < QCOLS)
                        rowmine8[cq * 2 + h] = outbox[Cp & 1][kk];
                }
            }
            __syncwarp();
            if (lane == 16 && doOut && I >= 5) {
                __threadfence();
                asm volatile("red.relaxed.gpu.global.add.u32 [%0], 1;"
                             :: "l"(myflag) : "memory");
            }
            if (I + 3 < SS4_CHUNKS) stageD(I + 3);
            if (lane < 16) {
                const int Cn = I + 1;
                if (doIn && Cn < 64) {
                    while (ldacq(prevflag) < Cn + 1) { }
                    inbox[Cn & 1][lane] = __ldg(&rowprev8[Cn * 16 + lane]);
                }
            }
            asm volatile("cp.async.wait_group 2;" ::: "memory");
            __syncthreads();
        }
    } else {
        const int is31 = (lane == 31);
        const int isLast = (s == NSTRIP4 - 1);
        const int pubp = is31 & !isLast;

        float L0 = 0.f, L1 = 0.f, L2 = 0.f, L3 = 0.f;
        float carry = 0.f;
        float sh0 = 0.f, sh1 = 0.f, sh2 = 0.f, sh3 = 0.f;
        int   M = 0, shM = 0;
        if (s == 0 && lane == 0) carry = 1.f;

        unsigned obase = (unsigned)__cvta_generic_to_shared(&outbox[0][0]);

        float outE = 1.f; int outM = 0;

        __syncthreads();

        for (int I = 0; I <= SS4_CHUNKS; ++I) {
            if (I < SS4_CHUNKS) {
#pragma unroll
                for (int q = 0; q < 8; ++q) {
                    const int c = I * 8 + q - lane;

                    const float4* Dq = Dbufp + (I & 3) * 1024 + q * 128 + lane;
                    float4 p0 = Dq[0];
                    float4 p1 = Dq[32];
                    float4 p2 = Dq[64];
                    float4 p3 = Dq[96];

                    float4 rE = inbox[I & 1][2 * q];
                    float  rM = inbox[I & 1][2 * q + 1].x;
                    if (I == 0 && q == 0 && s > 0 && lane == 0) M = (int)rM;

                    float nB0 = __shfl_up_sync(0xffffffffu, sh0, 1);
                    float nB1 = __shfl_up_sync(0xffffffffu, sh1, 1);
                    float nB2 = __shfl_up_sync(0xffffffffu, sh2, 1);
                    float nB3 = __shfl_up_sync(0xffffffffu, sh3, 1);
                    int   nM  = __shfl_up_sync(0xffffffffu, shM, 1);
                    if (lane == 0) { nB0 = rE.x; nB1 = rE.y; nB2 = rE.z; nB3 = rE.w; nM = (int)rM; }
                    if (c < 0) M = nM;
                    int dmm = M - nM;
                    dmm = dmm < -126 ? -126 : (dmm > 126 ? 126 : dmm);
                    float sc = __uint_as_float((unsigned)(dmm + 127) << 23);
                    float U0 = nB0 * sc, U1 = nB1 * sc, U2 = nB2 * sc, U3 = nB3 * sc;

                    float e00 = p0.x * ((carry + U0) + L0);
                    float e01 = p0.y * ((U0 + U1) + e00);
                    float e02 = p0.z * ((U1 + U2) + e01);
                    float e03 = p0.w * ((U2 + U3) + e02);
                    float e10 = p1.x * ((L0 + e00) + L1);
                    float e11 = p1.y * ((e00 + e01) + e10);
                    float e12 = p1.z * ((e01 + e02) + e11);
                    float e13 = p1.w * ((e02 + e03) + e12);
                    float e20 = p2.x * ((L1 + e10) + L2);
                    float e21 = p2.y * ((e10 + e11) + e20);
                    float e22 = p2.z * ((e11 + e12) + e21);
                    float e23 = p2.w * ((e12 + e13) + e22);
                    float e30 = p3.x * ((L2 + e20) + L3);
                    float e31 = p3.y * ((e20 + e21) + e30);
                    float e32 = p3.z * ((e21 + e22) + e31);
                    float e33 = p3.w * ((e22 + e23) + e32);

                    const int active = (c >= 0) & (c < QCOLS);

                    sts4_pred(obase + (unsigned)(((I & 1) * 16 + 2 * q) * 16),
                              e30, e31, e32, e33, pubp);
                    sts4_pred(obase + (unsigned)(((I & 1) * 16 + 2 * q + 1) * 16),
                              (float)M, 0.f, 0.f, 0.f, pubp);

                    outE = (is31 & isLast & active & (c == QCOLS - 1)) ? e33 : outE;
                    outM = (is31 & isLast & active & (c == QCOLS - 1)) ? M   : outM;

                    sh0 = active ? e30 : sh0;
                    sh1 = active ? e31 : sh1;
                    sh2 = active ? e32 : sh2;
                    sh3 = active ? e33 : sh3;
                    shM = active ? M   : shM;

                    int eb = (__float_as_int(e33) >> 23) & 255;
                    int doR = active & (eb > 0) & (eb < 254);
                    int dm = doR ? (eb - 127) : 0;
                    float scR = __uint_as_float((unsigned)(254 - (doR ? eb : 127)) << 23);
                    L0 = (active ? e03 : L0) * scR;
                    L1 = (active ? e13 : L1) * scR;
                    L2 = (active ? e23 : L2) * scR;
                    L3 = (active ? e33 : L3) * scR;
                    carry = U3 * scR;
                    M = M - dm;
                }
            }
            __syncthreads();
        }

        if (is31 && isLast)
            out[0] = ((float)outM - lg2f(outE)) * LN2;
    }
}

// ---------------- host orchestration ----------------
extern "C" void kernel_launch(void* const* d_in, const int* in_sizes, int n_in,
                              void* d_out, int out_size) {
    const float* x    = (const float*)d_in[0];
    const float* y    = (const float*)d_in[1];
    const float* Wih1 = (const float*)d_in[2];
    const float* Whh1 = (const float*)d_in[3];
    const float* bih1 = (const float*)d_in[4];
    const float* bhh1 = (const float*)d_in[5];
    const float* Wih2 = (const float*)d_in[6];
    const float* Whh2 = (const float*)d_in[7];
    const float* bih2 = (const float*)d_in[8];
    const float* bhh2 = (const float*)d_in[9];
    const float* W1   = (const float*)d_in[10];
    const float* b1   = (const float*)d_in[11];
    float* out = (float*)d_out;

    float *seq, *gi, *h1all, *whT1, *whT2;
    cudaGetSymbolAddress((void**)&seq,   g_seq);
    cudaGetSymbolAddress((void**)&gi,    g_gi);
    cudaGetSymbolAddress((void**)&h1all, g_h1all);
    cudaGetSymbolAddress((void**)&whT1,  g_WhhT1);
    cudaGetSymbolAddress((void**)&whT2,  g_WhhT2);

    const int DTW_SMEM = 65536 + 1024;
    cudaFuncSetAttribute(softdtw_ws4,
                         cudaFuncAttributeMaxDynamicSharedMemorySize, DTW_SMEM);

    // 1) prep
    {
        int total = STEPS * BATCH * IN_F;
        prep_kernel<<<(total + 255) / 256, 256>>>(x, y, Whh1, Whh2);
    }

    // 2) layer-1 input gates: seq @ Wih1^T  (K=72)
    sgemm_db<8><<<dim3(G3 / 128, (STEPS * BATCH) / 128), 256>>>(
        seq, Wih1, bih1, gi, STEPS * BATCH, G3, IN_F);

    // 3) layer-1 recurrence (warp-autonomous)
    gru_layer_kernel<<<BATCH / 16, 256>>>(
        gi, (const float4*)whT1, bhh1, h1all, nullptr, nullptr);

    // 4) layer-2 input gates: h1all @ Wih2^T  (K=128)
    sgemm_db<8><<<dim3(G3 / 128, (STEPS * BATCH) / 128), 256>>>(
        h1all, Wih2, bih2, gi, STEPS * BATCH, G3, HID);

    // 5) layer-2 recurrence + fused feature projection
    gru_layer_kernel<<<BATCH / 16, 256>>>(
        gi, (const float4*)whT2, bhh2, nullptr, W1, b1);

    // 6) pairwise distances
    pairdist_kernel<<<dim3(NW / 32, NW / 32), dim3(32, 32)>>>();

    // 7) soft-DTW
    softdtw_ws4<<<NSTRIP4, 64, DTW_SMEM>>>(out);
}